// round 8
// baseline (speedup 1.0000x reference)
#include <cuda_runtime.h>
#include <cuda_bf16.h>
#include <math.h>

#define B 8
#define D 256
#define T 2048
#define KNN 10
#define BETA 0.2f
#define THR 0.7f

// ---------------- scratch (device globals; no allocations allowed) ----------
__device__ float g_invn[B * T];
__device__ __nv_bfloat16 g_xnb[B * T * D];     // [B,T,D] normalized bf16, 8 MB
__device__ __nv_bfloat16 g_simb[B * T * T];    // [B,T,T] bf16, 64 MB
__device__ float g_rho[B * T];
__device__ float g_s[B * T];
__device__ int   g_ord[B * T];                 // rows sorted by rho desc
__device__ int   g_rank[B * T];                // inverse of g_ord
__device__ unsigned g_segmin[B * 32 * (T / 2)];// [b][seg][colpair] bf16x2, 1 MB
__device__ int   g_cstart[B * T];
__device__ int   g_clen[B * T];

// ---------------- 1) row norms of x^T ---------------------------------------
__global__ void norm_kernel(const float* __restrict__ x) {
    int idx = blockIdx.x * blockDim.x + threadIdx.x;   // over B*T
    int b = idx / T, t = idx % T;
    const float* xb = x + (size_t)b * D * T;
    float s = 0.f;
#pragma unroll 8
    for (int d = 0; d < D; d++) {
        float v = xb[d * T + t];
        s += v * v;
    }
    g_invn[idx] = 1.0f / fmaxf(sqrtf(s), 1e-12f);
}

// ---------------- 2) transpose + normalize -> bf16 [B,T,D] ------------------
__global__ void transpose_kernel(const float* __restrict__ x) {
    __shared__ float sh[32][33];
    int b = blockIdx.z;
    int t0 = blockIdx.x * 32, d0 = blockIdx.y * 32;
    int tx = threadIdx.x, ty = threadIdx.y;
    const float* xb = x + (size_t)b * D * T;
#pragma unroll
    for (int q = 0; q < 4; q++) {
        int d = d0 + ty + q * 8;
        sh[ty + q * 8][tx] = xb[d * T + t0 + tx];
    }
    __syncthreads();
#pragma unroll
    for (int q = 0; q < 4; q++) {
        int t = t0 + ty + q * 8;
        g_xnb[((size_t)b * T + t) * D + d0 + tx] =
            __float2bfloat16(sh[tx][ty + q * 8] * g_invn[b * T + t]);
    }
}

// ---------------- 3) sim = (xn @ xn^T + 1) * 0.5 via bf16 HMMA, bf16 store --
#define SKW 40   // smem row stride in bf16

#define LOAD_STAGE(stage, k0)                                                        \
    {                                                                                \
        _Pragma("unroll")                                                            \
        for (int q = 0; q < 2; q++) {                                                \
            int idx = tid + q * 256;                                                 \
            int r = idx >> 2, c = idx & 3;                                           \
            const __nv_bfloat16* srcA = Ab + (size_t)(row0 + r) * D + (k0) + c * 8;  \
            unsigned dA = (unsigned)__cvta_generic_to_shared(                        \
                &As[stage][r * SKW + c * 8]);                                        \
            asm volatile("cp.async.cg.shared.global [%0], [%1], 16;\n"               \
                         :: "r"(dA), "l"(srcA));                                     \
            const __nv_bfloat16* srcB = Ab + (size_t)(col0 + r) * D + (k0) + c * 8;  \
            unsigned dB = (unsigned)__cvta_generic_to_shared(                        \
                &Bs[stage][r * SKW + c * 8]);                                        \
            asm volatile("cp.async.cg.shared.global [%0], [%1], 16;\n"               \
                         :: "r"(dB), "l"(srcB));                                     \
        }                                                                            \
        asm volatile("cp.async.commit_group;\n");                                    \
    }

__global__ void __launch_bounds__(256) gemm_sim_kernel() {
    int b = blockIdx.z;
    const __nv_bfloat16* Ab = g_xnb + (size_t)b * T * D;
    __nv_bfloat16* C = g_simb + (size_t)b * T * T;
    int row0 = blockIdx.y * 128, col0 = blockIdx.x * 128;

    __shared__ __nv_bfloat16 As[2][128 * SKW];
    __shared__ __nv_bfloat16 Bs[2][128 * SKW];

    int tid = threadIdx.x;
    int wid = tid >> 5, lane = tid & 31;
    int wm = wid >> 1, wn = wid & 1;
    int g = lane >> 2, tg = lane & 3;

    float acc[2][8][4];
#pragma unroll
    for (int mt = 0; mt < 2; mt++)
#pragma unroll
        for (int nt = 0; nt < 8; nt++)
#pragma unroll
            for (int e = 0; e < 4; e++) acc[mt][nt][e] = 0.f;

    LOAD_STAGE(0, 0)

    for (int kt = 0; kt < 8; kt++) {
        if (kt < 7) {
            LOAD_STAGE((kt + 1) & 1, (kt + 1) * 32)
            asm volatile("cp.async.wait_group 1;\n");
        } else {
            asm volatile("cp.async.wait_group 0;\n");
        }
        __syncthreads();
        int st = kt & 1;
#pragma unroll
        for (int kk = 0; kk < 32; kk += 16) {
            unsigned af[2][4], bf[8][2];
#pragma unroll
            for (int mt = 0; mt < 2; mt++) {
                const __nv_bfloat16* base = &As[st][(wm * 32 + mt * 16 + g) * SKW + kk + tg * 2];
                af[mt][0] = *(const unsigned*)(base);
                af[mt][1] = *(const unsigned*)(base + 8 * SKW);
                af[mt][2] = *(const unsigned*)(base + 8);
                af[mt][3] = *(const unsigned*)(base + 8 * SKW + 8);
            }
#pragma unroll
            for (int nt = 0; nt < 8; nt++) {
                const __nv_bfloat16* base = &Bs[st][(wn * 64 + nt * 8 + g) * SKW + kk + tg * 2];
                bf[nt][0] = *(const unsigned*)(base);
                bf[nt][1] = *(const unsigned*)(base + 8);
            }
#pragma unroll
            for (int mt = 0; mt < 2; mt++)
#pragma unroll
                for (int nt = 0; nt < 8; nt++) {
                    asm volatile(
                        "mma.sync.aligned.m16n8k16.row.col.f32.bf16.bf16.f32 "
                        "{%0,%1,%2,%3},{%4,%5,%6,%7},{%8,%9},{%0,%1,%2,%3};\n"
                        : "+f"(acc[mt][nt][0]), "+f"(acc[mt][nt][1]),
                          "+f"(acc[mt][nt][2]), "+f"(acc[mt][nt][3])
                        : "r"(af[mt][0]), "r"(af[mt][1]), "r"(af[mt][2]), "r"(af[mt][3]),
                          "r"(bf[nt][0]), "r"(bf[nt][1]));
                }
        }
        __syncthreads();
    }

#pragma unroll
    for (int mt = 0; mt < 2; mt++) {
        int r = row0 + wm * 32 + mt * 16 + g;
#pragma unroll
        for (int nt = 0; nt < 8; nt++) {
            int c = col0 + wn * 64 + nt * 8 + tg * 2;
            __nv_bfloat162 p0 = __floats2bfloat162_rn((acc[mt][nt][0] + 1.f) * 0.5f,
                                                      (acc[mt][nt][1] + 1.f) * 0.5f);
            __nv_bfloat162 p1 = __floats2bfloat162_rn((acc[mt][nt][2] + 1.f) * 0.5f,
                                                      (acc[mt][nt][3] + 1.f) * 0.5f);
            *(__nv_bfloat162*)&C[(size_t)r * T + c] = p0;
            *(__nv_bfloat162*)&C[(size_t)(r + 8) * T + c] = p1;
        }
    }
}

// ---------------- 4) rho: top-11 per row (bf16), drop max (self) ------------
__device__ __forceinline__ void ins11(float v, float* a) {
#pragma unroll
    for (int k = 0; k < 11; k++) {
        if (v > a[k]) { float tmp = a[k]; a[k] = v; v = tmp; }
    }
}

__global__ void rho_kernel() {
    int row = (blockIdx.x * blockDim.x + threadIdx.x) >> 5;
    int lane = threadIdx.x & 31;
    const uint4* r16 = (const uint4*)(g_simb + (size_t)row * T);   // 256 uint4/row

    float a[11];
#pragma unroll
    for (int k = 0; k < 11; k++) a[k] = -1e30f;

#pragma unroll
    for (int it = 0; it < 4; it++) {
        uint4 v0 = r16[lane + (2 * it) * 32];
        uint4 v1 = r16[lane + (2 * it + 1) * 32];
        __nv_bfloat162 p[8];
        p[0] = *(__nv_bfloat162*)&v0.x; p[1] = *(__nv_bfloat162*)&v0.y;
        p[2] = *(__nv_bfloat162*)&v0.z; p[3] = *(__nv_bfloat162*)&v0.w;
        p[4] = *(__nv_bfloat162*)&v1.x; p[5] = *(__nv_bfloat162*)&v1.y;
        p[6] = *(__nv_bfloat162*)&v1.z; p[7] = *(__nv_bfloat162*)&v1.w;
        __nv_bfloat162 m01 = __hmax2(p[0], p[1]), m23 = __hmax2(p[2], p[3]);
        __nv_bfloat162 m45 = __hmax2(p[4], p[5]), m67 = __hmax2(p[6], p[7]);
        __nv_bfloat162 m = __hmax2(__hmax2(m01, m23), __hmax2(m45, m67));
        float fm = fmaxf(__low2float(m), __high2float(m));
        if (fm > a[10]) {
#pragma unroll
            for (int q = 0; q < 8; q++) {
                float lo = __low2float(p[q]), hi = __high2float(p[q]);
                if (lo > a[10]) ins11(lo, a);
                if (hi > a[10]) ins11(hi, a);
            }
        }
    }
    float sum = 0.f;
#pragma unroll
    for (int r = 0; r < 11; r++) {
        float h = a[0], m = h;
#pragma unroll
        for (int o = 16; o > 0; o >>= 1) m = fmaxf(m, __shfl_xor_sync(0xffffffffu, m, o));
        unsigned msk = __ballot_sync(0xffffffffu, h == m);
        int winner = __ffs(msk) - 1;
        if (lane == winner) {
#pragma unroll
            for (int k = 0; k < 10; k++) a[k] = a[k + 1];
            a[10] = -1e30f;
        }
        if (r > 0) sum += m;   // ranks 1..10 (rank 0 = self)
    }
    if (lane == 0) g_rho[row] = expf(-sum * (1.0f / KNN));
}

// ---------------- sorting helper (block of 1024, keys in smem) --------------
__device__ __forceinline__ void bitonic_sort_shared(float* key, int* ord) {
    for (int k = 2; k <= T; k <<= 1) {
        for (int j = k >> 1; j > 0; j >>= 1) {
#pragma unroll 2
            for (int i = threadIdx.x; i < T; i += 1024) {
                int l = i ^ j;
                if (l > i) {
                    bool up = ((i & k) == 0);
                    float ki = key[i], kl = key[l];
                    int oi = ord[i], ol = ord[l];
                    bool iAfter = (ki > kl) || (ki == kl && oi > ol);
                    if (iAfter == up) {
                        key[i] = kl; key[l] = ki;
                        ord[i] = ol; ord[l] = oi;
                    }
                }
            }
            __syncthreads();
        }
    }
}

// ---------------- 5a) sort rows by rho desc ---------------------------------
__global__ void __launch_bounds__(1024) sort_rho_kernel() {
    __shared__ float key[T];
    __shared__ int ord[T];
    int b = blockIdx.x, tid = threadIdx.x;
    for (int t = tid; t < T; t += 1024) { key[t] = -g_rho[b * T + t]; ord[t] = t; }
    __syncthreads();
    bitonic_sort_shared(key, ord);
    for (int k = tid; k < T; k += 1024) {
        int t = ord[k];
        g_ord[b * T + k] = t;
        g_rank[b * T + t] = k;
    }
}

// ---------------- 5b) segment mins over rho-ordered rows --------------------
// grid (colchunk=4, seg=32, b), block 256: thread owns one bf16x2 column pair.
__global__ void __launch_bounds__(256) segmin_kernel() {
    __shared__ int rows[64];
    int b = blockIdx.z, seg = blockIdx.y, cc = blockIdx.x;
    int tid = threadIdx.x;
    if (tid < 64) rows[tid] = g_ord[b * T + seg * 64 + tid];
    __syncthreads();
    int cp = cc * 256 + tid;                     // column-pair index (0..1023)
    const __nv_bfloat16* S = g_simb + (size_t)b * T * T;
    __nv_bfloat162 run = __floats2bfloat162_rn(1e30f, 1e30f);
#pragma unroll 8
    for (int k = 0; k < 64; k++) {
        unsigned u = *(const unsigned*)(S + (size_t)rows[k] * T + cp * 2);
        run = __hmin2(run, *(__nv_bfloat162*)&u);
    }
    g_segmin[((size_t)b * 32 + seg) * (T / 2) + cp] = *(unsigned*)&run;
}

// ---------------- 5c) delta fix-up + s = rho*delta --------------------------
__global__ void deltafix_kernel() {
    int idx = blockIdx.x * blockDim.x + threadIdx.x;   // over B*T
    int b = idx / T, i = idx % T;
    float rho_i = g_rho[idx];
    int r = g_rank[idx];
    int seg_i = r >> 6;

    float mn = 1e30f;
    const unsigned* segm = g_segmin + (size_t)b * 32 * (T / 2) + (i >> 1);
    for (int s = 0; s < seg_i; s++) {
        unsigned u = segm[(size_t)s * (T / 2)];
        __nv_bfloat162 p = *(__nv_bfloat162*)&u;
        float v = (i & 1) ? __high2float(p) : __low2float(p);
        mn = fminf(mn, v);
    }
    const int* ord = g_ord + b * T + (seg_i << 6);
    const __nv_bfloat16* S = g_simb + (size_t)b * T * T;
    int nown = r - (seg_i << 6);
    for (int k = 0; k < nown; k++) {
        int row = ord[k];
        if (g_rho[b * T + row] > rho_i)   // strict: ties excluded (matches ref)
            mn = fminf(mn, __bfloat162float(S[(size_t)row * T + i]));
    }
    float delta = (mn < 1e29f) ? mn
                               : __bfloat162float(S[(size_t)i * T + i]); // row max = diag
    g_s[idx] = rho_i * delta;
}

// ---------------- 6) clustering (one block of 1024 per batch) ---------------
// dynamic smem: s_sh[T] | key[T] | ordA[T] | lenA[T] | staA[T] | thr[T]
//               | asgw[66] | ncl  ->  (6*T + 67) * 4
__global__ void __launch_bounds__(1024) cluster_kernel(float* lens_out) {
    extern __shared__ char smem[];
    float* s_sh = (float*)smem;
    float* key  = s_sh + T;
    int* ordA = (int*)(key + T);
    int* lenA = ordA + T;
    int* staA = lenA + T;
    unsigned* thr_sh = (unsigned*)(staA + T);
    unsigned* asgw = thr_sh + T;
    int* sh_ncl = (int*)(asgw + 66);

    int b = blockIdx.x;
    int tid = threadIdx.x;

    for (int t = tid; t < T; t += 1024) s_sh[t] = g_s[b * T + t];
    for (int t = tid; t < 66; t += 1024) asgw[t] = 0u;
    __syncthreads();

    // per-frame 9-bit neighbor-threshold mask: bit k <-> time t-4+k (k!=4)
    for (int t = tid; t < T; t += 1024) {
        unsigned m = 0;
        const __nv_bfloat16* row = g_simb + ((size_t)b * T + t) * T;
#pragma unroll
        for (int k = 0; k < 9; k++) {
            if (k == 4) continue;
            int j = t - 4 + k;
            if (j >= 0 && j < T &&
                (__bfloat162float(row[j]) - BETA * s_sh[j] > THR)) m |= 1u << k;
        }
        thr_sh[t] = m;
    }

    for (int t = tid; t < T; t += 1024) { key[t] = -s_sh[t]; ordA[t] = t; }
    __syncthreads();
    bitonic_sort_shared(key, ordA);

    if (tid < 32) {
        const unsigned full = 0xffffffffu;
        int lane = tid;
        int cid_base = 0;
        for (int p = 0; p < T; p += 32) {
            int seed = ordA[p + lane];
            unsigned thrm = thr_sh[seed];
            int bitpos = seed + 28;
            unsigned w0 = asgw[bitpos >> 5];
            unsigned w1 = asgw[(bitpos >> 5) + 1];
            unsigned A = (unsigned)(((((unsigned long long)w1 << 32) | w0)
                                     >> (bitpos & 31))) & 0x1FFu;
            bool pre = (A >> 4) & 1u;
            bool isfast = !pre && (thrm == 0u);
            bool isslow = !pre && (thrm != 0u);
            unsigned slowm = __ballot_sync(full, isslow);
            bool committed = false;
            int st = seed, sz = 1;

            if (slowm == 0u) {
                committed = isfast;
            } else {
                unsigned rem = slowm;
                while (rem) {
                    int i = __ffs(rem) - 1; rem &= rem - 1;
                    int wb_i = __shfl_sync(full, seed, i) - 4;
                    unsigned contrib = 0u;
                    int lo = -1, hi = -2;
                    if (committed) {
                        lo = max(st, wb_i); hi = min(st + sz - 1, wb_i + 8);
                    } else if (isfast && lane < i) {
                        lo = max(seed, wb_i); hi = min(seed, wb_i + 8);
                    }
                    if (lo <= hi) contrib = ((1u << (hi - lo + 1)) - 1u) << (lo - wb_i);
                    unsigned add = __reduce_or_sync(full, contrib);
                    if (lane == i) {
                        A |= add;
                        if (!((A >> 4) & 1u)) {
                            unsigned avail = thrm & ~A;
                            unsigned f4 = (avail >> 5) & 0xFu;
                            int f = min(__ffs(~f4) - 1, 3);
                            int size = 1 + f;
                            unsigned b4 = __brev(avail & 0xFu) >> 28;
                            int bb = min(__ffs(~b4) - 1, 4 - size);
                            st = seed - bb;
                            sz = size + bb;
                            committed = true;
                        }
                    }
                }
                unsigned cm = slowm;
                bool covered = false;
                while (cm) {
                    int j = __ffs(cm) - 1; cm &= cm - 1;
                    int stj = __shfl_sync(full, st, j);
                    int szj = __shfl_sync(full, sz, j);
                    int cmj = __shfl_sync(full, (int)committed, j);
                    if (isfast && j < lane && cmj && seed >= stj && seed < stj + szj)
                        covered = true;
                }
                if (isfast && !covered) committed = true;
            }

            unsigned cmask = __ballot_sync(full, committed);
            if (committed) {
                int cid = cid_base + __popc(cmask & ((1u << lane) - 1u));
                lenA[cid] = sz;
                staA[cid] = st;
                int bp = st + 32;
                unsigned long long m64 = ((1ull << sz) - 1ull) << (bp & 31);
                atomicOr(&asgw[bp >> 5], (unsigned)m64);
                unsigned hiw = (unsigned)(m64 >> 32);
                if (hiw) atomicOr(&asgw[(bp >> 5) + 1], hiw);
            }
            cid_base += __popc(cmask);
            __syncwarp(full);
        }
        if (lane == 0) *sh_ncl = cid_base;
    }
    __syncthreads();

    int ncl = *sh_ncl;
    for (int c = tid; c < T; c += 1024) {
        if (c >= ncl) { lenA[c] = 0; staA[c] = T; }
        key[c] = (float)(staA[c] * 4096 + c);
        ordA[c] = c;
    }
    __syncthreads();
    bitonic_sort_shared(key, ordA);

    for (int r = tid; r < T; r += 1024) {
        int c = ordA[r];
        g_clen[b * T + r] = lenA[c];
        g_cstart[b * T + r] = staA[c];
        if (lens_out) lens_out[b * T + r] = (float)lenA[c];
    }
}

// ---------------- 7) mean-pool per cluster (members contiguous) -------------
__global__ void pool_kernel(const float* __restrict__ x, float* __restrict__ out) {
    int idx = blockIdx.x * blockDim.x + threadIdx.x;   // over B*D*T
    int r = idx % T;
    int d = (idx / T) % D;
    int b = idx / (T * D);
    int len = g_clen[b * T + r];
    int st = g_cstart[b * T + r];
    float acc = 0.f;
    for (int k = 0; k < len; k++) acc += x[((size_t)b * D + d) * T + st + k];
    out[idx] = len ? acc / (float)len : 0.f;
}

// ---------------- launch -----------------------------------------------------
extern "C" void kernel_launch(void* const* d_in, const int* in_sizes, int n_in,
                              void* d_out, int out_size) {
    const float* x = (const float*)d_in[0];
    float* out = (float*)d_out;
    float* lens_out = (out_size >= (int)(B * D * T + B * T)) ? out + (size_t)B * D * T
                                                             : nullptr;

    const int CLU_SMEM = (6 * T + 67) * 4;
    cudaFuncSetAttribute(cluster_kernel,
                         cudaFuncAttributeMaxDynamicSharedMemorySize, CLU_SMEM);

    norm_kernel<<<(B * T) / 256, 256>>>(x);
    transpose_kernel<<<dim3(T / 32, D / 32, B), dim3(32, 8)>>>(x);
    gemm_sim_kernel<<<dim3(T / 128, T / 128, B), 256>>>();
    rho_kernel<<<(B * T * 32) / 256, 256>>>();
    sort_rho_kernel<<<B, 1024>>>();
    segmin_kernel<<<dim3(4, 32, B), 256>>>();
    deltafix_kernel<<<(B * T) / 256, 256>>>();
    cluster_kernel<<<B, 1024, CLU_SMEM>>>(lens_out);
    pool_kernel<<<(B * D * T) / 256, 256>>>(x, out);
}

// round 9
// speedup vs baseline: 7.4094x; 7.4094x over previous
#include <cuda_runtime.h>
#include <cuda_bf16.h>
#include <math.h>

#define B 8
#define D 256
#define T 2048
#define KNN 10
#define BETA 0.2f
#define THR 0.7f

// ---------------- scratch (device globals; no allocations allowed) ----------
__device__ float g_invn[B * T];
__device__ __nv_bfloat16 g_xnb[B * T * D];     // [B,T,D] normalized bf16, 8 MB
__device__ __nv_bfloat16 g_simb[B * T * T];    // [B,T,T] bf16, 64 MB
__device__ float g_rho[B * T];
__device__ float g_s[B * T];
__device__ int   g_ord[B * T];
__device__ int   g_rank[B * T];
__device__ unsigned g_segmin[B * 32 * (T / 2)];
__device__ int   g_cstart[B * T];
__device__ int   g_clen[B * T];
__device__ int   g_flag;                       // 0 = all-singleton fast path

// ---------------- 0) flag reset ---------------------------------------------
__global__ void reset_flag_kernel() { g_flag = 0; }

// ---------------- 1) row norms of x^T ---------------------------------------
__global__ void norm_kernel(const float* __restrict__ x) {
    int idx = blockIdx.x * blockDim.x + threadIdx.x;   // over B*T
    int b = idx / T, t = idx % T;
    const float* xb = x + (size_t)b * D * T;
    float s = 0.f;
#pragma unroll 8
    for (int d = 0; d < D; d++) {
        float v = xb[d * T + t];
        s += v * v;
    }
    g_invn[idx] = 1.0f / fmaxf(sqrtf(s), 1e-12f);
}

// ---------------- 2) transpose + normalize -> bf16 [B,T,D] ------------------
__global__ void transpose_kernel(const float* __restrict__ x) {
    __shared__ float sh[32][33];
    int b = blockIdx.z;
    int t0 = blockIdx.x * 32, d0 = blockIdx.y * 32;
    int tx = threadIdx.x, ty = threadIdx.y;
    const float* xb = x + (size_t)b * D * T;
#pragma unroll
    for (int q = 0; q < 4; q++) {
        int d = d0 + ty + q * 8;
        sh[ty + q * 8][tx] = xb[d * T + t0 + tx];
    }
    __syncthreads();
#pragma unroll
    for (int q = 0; q < 4; q++) {
        int t = t0 + ty + q * 8;
        g_xnb[((size_t)b * T + t) * D + d0 + tx] =
            __float2bfloat16(sh[tx][ty + q * 8] * g_invn[b * T + t]);
    }
}

// ---------------- 2b) gate: any band sim possibly > THR? --------------------
// Growth needs sim - BETA*s > THR with s >= 0 (rho>0, delta in [0,1]),
// hence sim > THR on the +/-4 band. Gate conservatively at sim > 0.68
// (dot > 0.36); bf16 dot error << 0.02 margin. One warp per (b,t).
__global__ void gate_kernel() {
    int gw = (blockIdx.x * blockDim.x + threadIdx.x) >> 5;   // b*T + t
    int lane = threadIdx.x & 31;
    int t = gw % T;
    const uint4* row = (const uint4*)(g_xnb + (size_t)gw * D);   // 32 uint4

    uint4 a4 = row[lane];
    __nv_bfloat162 a[4];
    a[0] = *(__nv_bfloat162*)&a4.x; a[1] = *(__nv_bfloat162*)&a4.y;
    a[2] = *(__nv_bfloat162*)&a4.z; a[3] = *(__nv_bfloat162*)&a4.w;

    float mx = -1.f;
#pragma unroll
    for (int off = 1; off <= 4; off++) {
        float acc = 0.f;
        if (t + off < T) {
            uint4 b4 = row[lane + off * 32];
            __nv_bfloat162 bb[4];
            bb[0] = *(__nv_bfloat162*)&b4.x; bb[1] = *(__nv_bfloat162*)&b4.y;
            bb[2] = *(__nv_bfloat162*)&b4.z; bb[3] = *(__nv_bfloat162*)&b4.w;
#pragma unroll
            for (int q = 0; q < 4; q++) {
                float2 fa = __bfloat1622float2(a[q]);
                float2 fb = __bfloat1622float2(bb[q]);
                acc += fa.x * fb.x + fa.y * fb.y;
            }
        }
#pragma unroll
        for (int o = 16; o > 0; o >>= 1)
            acc += __shfl_xor_sync(0xffffffffu, acc, o);
        mx = fmaxf(mx, acc);
    }
    if (lane == 0 && mx > 0.36f) atomicOr(&g_flag, 1);   // sim=(dot+1)/2 > 0.68
}

// ---------------- 3) sim GEMM (fallback only) --------------------------------
#define SKW 40

#define LOAD_STAGE(stage, k0)                                                        \
    {                                                                                \
        _Pragma("unroll")                                                            \
        for (int q = 0; q < 2; q++) {                                                \
            int idx = tid + q * 256;                                                 \
            int r = idx >> 2, c = idx & 3;                                           \
            const __nv_bfloat16* srcA = Ab + (size_t)(row0 + r) * D + (k0) + c * 8;  \
            unsigned dA = (unsigned)__cvta_generic_to_shared(                        \
                &As[stage][r * SKW + c * 8]);                                        \
            asm volatile("cp.async.cg.shared.global [%0], [%1], 16;\n"               \
                         :: "r"(dA), "l"(srcA));                                     \
            const __nv_bfloat16* srcB = Ab + (size_t)(col0 + r) * D + (k0) + c * 8;  \
            unsigned dB = (unsigned)__cvta_generic_to_shared(                        \
                &Bs[stage][r * SKW + c * 8]);                                        \
            asm volatile("cp.async.cg.shared.global [%0], [%1], 16;\n"               \
                         :: "r"(dB), "l"(srcB));                                     \
        }                                                                            \
        asm volatile("cp.async.commit_group;\n");                                    \
    }

__global__ void __launch_bounds__(256) gemm_sim_kernel() {
    if (g_flag == 0) return;
    int b = blockIdx.z;
    const __nv_bfloat16* Ab = g_xnb + (size_t)b * T * D;
    __nv_bfloat16* C = g_simb + (size_t)b * T * T;
    int row0 = blockIdx.y * 128, col0 = blockIdx.x * 128;

    __shared__ __nv_bfloat16 As[2][128 * SKW];
    __shared__ __nv_bfloat16 Bs[2][128 * SKW];

    int tid = threadIdx.x;
    int wid = tid >> 5, lane = tid & 31;
    int wm = wid >> 1, wn = wid & 1;
    int g = lane >> 2, tg = lane & 3;

    float acc[2][8][4];
#pragma unroll
    for (int mt = 0; mt < 2; mt++)
#pragma unroll
        for (int nt = 0; nt < 8; nt++)
#pragma unroll
            for (int e = 0; e < 4; e++) acc[mt][nt][e] = 0.f;

    LOAD_STAGE(0, 0)

    for (int kt = 0; kt < 8; kt++) {
        if (kt < 7) {
            LOAD_STAGE((kt + 1) & 1, (kt + 1) * 32)
            asm volatile("cp.async.wait_group 1;\n");
        } else {
            asm volatile("cp.async.wait_group 0;\n");
        }
        __syncthreads();
        int st = kt & 1;
#pragma unroll
        for (int kk = 0; kk < 32; kk += 16) {
            unsigned af[2][4], bf[8][2];
#pragma unroll
            for (int mt = 0; mt < 2; mt++) {
                const __nv_bfloat16* base = &As[st][(wm * 32 + mt * 16 + g) * SKW + kk + tg * 2];
                af[mt][0] = *(const unsigned*)(base);
                af[mt][1] = *(const unsigned*)(base + 8 * SKW);
                af[mt][2] = *(const unsigned*)(base + 8);
                af[mt][3] = *(const unsigned*)(base + 8 * SKW + 8);
            }
#pragma unroll
            for (int nt = 0; nt < 8; nt++) {
                const __nv_bfloat16* base = &Bs[st][(wn * 64 + nt * 8 + g) * SKW + kk + tg * 2];
                bf[nt][0] = *(const unsigned*)(base);
                bf[nt][1] = *(const unsigned*)(base + 8);
            }
#pragma unroll
            for (int mt = 0; mt < 2; mt++)
#pragma unroll
                for (int nt = 0; nt < 8; nt++) {
                    asm volatile(
                        "mma.sync.aligned.m16n8k16.row.col.f32.bf16.bf16.f32 "
                        "{%0,%1,%2,%3},{%4,%5,%6,%7},{%8,%9},{%0,%1,%2,%3};\n"
                        : "+f"(acc[mt][nt][0]), "+f"(acc[mt][nt][1]),
                          "+f"(acc[mt][nt][2]), "+f"(acc[mt][nt][3])
                        : "r"(af[mt][0]), "r"(af[mt][1]), "r"(af[mt][2]), "r"(af[mt][3]),
                          "r"(bf[nt][0]), "r"(bf[nt][1]));
                }
        }
        __syncthreads();
    }

#pragma unroll
    for (int mt = 0; mt < 2; mt++) {
        int r = row0 + wm * 32 + mt * 16 + g;
#pragma unroll
        for (int nt = 0; nt < 8; nt++) {
            int c = col0 + wn * 64 + nt * 8 + tg * 2;
            __nv_bfloat162 p0 = __floats2bfloat162_rn((acc[mt][nt][0] + 1.f) * 0.5f,
                                                      (acc[mt][nt][1] + 1.f) * 0.5f);
            __nv_bfloat162 p1 = __floats2bfloat162_rn((acc[mt][nt][2] + 1.f) * 0.5f,
                                                      (acc[mt][nt][3] + 1.f) * 0.5f);
            *(__nv_bfloat162*)&C[(size_t)r * T + c] = p0;
            *(__nv_bfloat162*)&C[(size_t)(r + 8) * T + c] = p1;
        }
    }
}

// ---------------- 4) rho (fallback only) -------------------------------------
__device__ __forceinline__ void ins11(float v, float* a) {
#pragma unroll
    for (int k = 0; k < 11; k++) {
        if (v > a[k]) { float tmp = a[k]; a[k] = v; v = tmp; }
    }
}

__global__ void rho_kernel() {
    if (g_flag == 0) return;
    int row = (blockIdx.x * blockDim.x + threadIdx.x) >> 5;
    int lane = threadIdx.x & 31;
    const uint4* r16 = (const uint4*)(g_simb + (size_t)row * T);

    float a[11];
#pragma unroll
    for (int k = 0; k < 11; k++) a[k] = -1e30f;

#pragma unroll
    for (int it = 0; it < 4; it++) {
        uint4 v0 = r16[lane + (2 * it) * 32];
        uint4 v1 = r16[lane + (2 * it + 1) * 32];
        __nv_bfloat162 p[8];
        p[0] = *(__nv_bfloat162*)&v0.x; p[1] = *(__nv_bfloat162*)&v0.y;
        p[2] = *(__nv_bfloat162*)&v0.z; p[3] = *(__nv_bfloat162*)&v0.w;
        p[4] = *(__nv_bfloat162*)&v1.x; p[5] = *(__nv_bfloat162*)&v1.y;
        p[6] = *(__nv_bfloat162*)&v1.z; p[7] = *(__nv_bfloat162*)&v1.w;
        __nv_bfloat162 m01 = __hmax2(p[0], p[1]), m23 = __hmax2(p[2], p[3]);
        __nv_bfloat162 m45 = __hmax2(p[4], p[5]), m67 = __hmax2(p[6], p[7]);
        __nv_bfloat162 m = __hmax2(__hmax2(m01, m23), __hmax2(m45, m67));
        float fm = fmaxf(__low2float(m), __high2float(m));
        if (fm > a[10]) {
#pragma unroll
            for (int q = 0; q < 8; q++) {
                float lo = __low2float(p[q]), hi = __high2float(p[q]);
                if (lo > a[10]) ins11(lo, a);
                if (hi > a[10]) ins11(hi, a);
            }
        }
    }
    float sum = 0.f;
#pragma unroll
    for (int r = 0; r < 11; r++) {
        float h = a[0], m = h;
#pragma unroll
        for (int o = 16; o > 0; o >>= 1) m = fmaxf(m, __shfl_xor_sync(0xffffffffu, m, o));
        unsigned msk = __ballot_sync(0xffffffffu, h == m);
        int winner = __ffs(msk) - 1;
        if (lane == winner) {
#pragma unroll
            for (int k = 0; k < 10; k++) a[k] = a[k + 1];
            a[10] = -1e30f;
        }
        if (r > 0) sum += m;
    }
    if (lane == 0) g_rho[row] = expf(-sum * (1.0f / KNN));
}

// ---------------- sorting helper ---------------------------------------------
__device__ __forceinline__ void bitonic_sort_shared(float* key, int* ord) {
    for (int k = 2; k <= T; k <<= 1) {
        for (int j = k >> 1; j > 0; j >>= 1) {
#pragma unroll 2
            for (int i = threadIdx.x; i < T; i += 1024) {
                int l = i ^ j;
                if (l > i) {
                    bool up = ((i & k) == 0);
                    float ki = key[i], kl = key[l];
                    int oi = ord[i], ol = ord[l];
                    bool iAfter = (ki > kl) || (ki == kl && oi > ol);
                    if (iAfter == up) {
                        key[i] = kl; key[l] = ki;
                        ord[i] = ol; ord[l] = oi;
                    }
                }
            }
            __syncthreads();
        }
    }
}

// ---------------- 5a) sort rows by rho desc (fallback only) ------------------
__global__ void __launch_bounds__(1024) sort_rho_kernel() {
    if (g_flag == 0) return;
    __shared__ float key[T];
    __shared__ int ord[T];
    int b = blockIdx.x, tid = threadIdx.x;
    for (int t = tid; t < T; t += 1024) { key[t] = -g_rho[b * T + t]; ord[t] = t; }
    __syncthreads();
    bitonic_sort_shared(key, ord);
    for (int k = tid; k < T; k += 1024) {
        int t = ord[k];
        g_ord[b * T + k] = t;
        g_rank[b * T + t] = k;
    }
}

// ---------------- 5b) segment mins (fallback only) ---------------------------
__global__ void __launch_bounds__(256) segmin_kernel() {
    if (g_flag == 0) return;
    __shared__ int rows[64];
    int b = blockIdx.z, seg = blockIdx.y, cc = blockIdx.x;
    int tid = threadIdx.x;
    if (tid < 64) rows[tid] = g_ord[b * T + seg * 64 + tid];
    __syncthreads();
    int cp = cc * 256 + tid;
    const __nv_bfloat16* S = g_simb + (size_t)b * T * T;
    __nv_bfloat162 run = __floats2bfloat162_rn(1e30f, 1e30f);
#pragma unroll 8
    for (int k = 0; k < 64; k++) {
        unsigned u = *(const unsigned*)(S + (size_t)rows[k] * T + cp * 2);
        run = __hmin2(run, *(__nv_bfloat162*)&u);
    }
    g_segmin[((size_t)b * 32 + seg) * (T / 2) + cp] = *(unsigned*)&run;
}

// ---------------- 5c) delta fix-up (fallback only) ---------------------------
__global__ void deltafix_kernel() {
    if (g_flag == 0) return;
    int idx = blockIdx.x * blockDim.x + threadIdx.x;
    int b = idx / T, i = idx % T;
    float rho_i = g_rho[idx];
    int r = g_rank[idx];
    int seg_i = r >> 6;

    float mn = 1e30f;
    const unsigned* segm = g_segmin + (size_t)b * 32 * (T / 2) + (i >> 1);
    for (int s = 0; s < seg_i; s++) {
        unsigned u = segm[(size_t)s * (T / 2)];
        __nv_bfloat162 p = *(__nv_bfloat162*)&u;
        float v = (i & 1) ? __high2float(p) : __low2float(p);
        mn = fminf(mn, v);
    }
    const int* ord = g_ord + b * T + (seg_i << 6);
    const __nv_bfloat16* S = g_simb + (size_t)b * T * T;
    int nown = r - (seg_i << 6);
    for (int k = 0; k < nown; k++) {
        int row = ord[k];
        if (g_rho[b * T + row] > rho_i)
            mn = fminf(mn, __bfloat162float(S[(size_t)row * T + i]));
    }
    float delta = (mn < 1e29f) ? mn
                               : __bfloat162float(S[(size_t)i * T + i]);
    g_s[idx] = rho_i * delta;
}

// ---------------- 6) clustering (fallback only) ------------------------------
__global__ void __launch_bounds__(1024) cluster_kernel(float* lens_out) {
    if (g_flag == 0) return;
    extern __shared__ char smem[];
    float* s_sh = (float*)smem;
    float* key  = s_sh + T;
    int* ordA = (int*)(key + T);
    int* lenA = ordA + T;
    int* staA = lenA + T;
    unsigned* thr_sh = (unsigned*)(staA + T);
    unsigned* asgw = thr_sh + T;
    int* sh_ncl = (int*)(asgw + 66);

    int b = blockIdx.x;
    int tid = threadIdx.x;

    for (int t = tid; t < T; t += 1024) s_sh[t] = g_s[b * T + t];
    for (int t = tid; t < 66; t += 1024) asgw[t] = 0u;
    __syncthreads();

    for (int t = tid; t < T; t += 1024) {
        unsigned m = 0;
        const __nv_bfloat16* row = g_simb + ((size_t)b * T + t) * T;
#pragma unroll
        for (int k = 0; k < 9; k++) {
            if (k == 4) continue;
            int j = t - 4 + k;
            if (j >= 0 && j < T &&
                (__bfloat162float(row[j]) - BETA * s_sh[j] > THR)) m |= 1u << k;
        }
        thr_sh[t] = m;
    }

    for (int t = tid; t < T; t += 1024) { key[t] = -s_sh[t]; ordA[t] = t; }
    __syncthreads();
    bitonic_sort_shared(key, ordA);

    if (tid < 32) {
        const unsigned full = 0xffffffffu;
        int lane = tid;
        int cid_base = 0;
        for (int p = 0; p < T; p += 32) {
            int seed = ordA[p + lane];
            unsigned thrm = thr_sh[seed];
            int bitpos = seed + 28;
            unsigned w0 = asgw[bitpos >> 5];
            unsigned w1 = asgw[(bitpos >> 5) + 1];
            unsigned A = (unsigned)(((((unsigned long long)w1 << 32) | w0)
                                     >> (bitpos & 31))) & 0x1FFu;
            bool pre = (A >> 4) & 1u;
            bool isfast = !pre && (thrm == 0u);
            bool isslow = !pre && (thrm != 0u);
            unsigned slowm = __ballot_sync(full, isslow);
            bool committed = false;
            int st = seed, sz = 1;

            if (slowm == 0u) {
                committed = isfast;
            } else {
                unsigned rem = slowm;
                while (rem) {
                    int i = __ffs(rem) - 1; rem &= rem - 1;
                    int wb_i = __shfl_sync(full, seed, i) - 4;
                    unsigned contrib = 0u;
                    int lo = -1, hi = -2;
                    if (committed) {
                        lo = max(st, wb_i); hi = min(st + sz - 1, wb_i + 8);
                    } else if (isfast && lane < i) {
                        lo = max(seed, wb_i); hi = min(seed, wb_i + 8);
                    }
                    if (lo <= hi) contrib = ((1u << (hi - lo + 1)) - 1u) << (lo - wb_i);
                    unsigned add = __reduce_or_sync(full, contrib);
                    if (lane == i) {
                        A |= add;
                        if (!((A >> 4) & 1u)) {
                            unsigned avail = thrm & ~A;
                            unsigned f4 = (avail >> 5) & 0xFu;
                            int f = min(__ffs(~f4) - 1, 3);
                            int size = 1 + f;
                            unsigned b4 = __brev(avail & 0xFu) >> 28;
                            int bb = min(__ffs(~b4) - 1, 4 - size);
                            st = seed - bb;
                            sz = size + bb;
                            committed = true;
                        }
                    }
                }
                unsigned cm = slowm;
                bool covered = false;
                while (cm) {
                    int j = __ffs(cm) - 1; cm &= cm - 1;
                    int stj = __shfl_sync(full, st, j);
                    int szj = __shfl_sync(full, sz, j);
                    int cmj = __shfl_sync(full, (int)committed, j);
                    if (isfast && j < lane && cmj && seed >= stj && seed < stj + szj)
                        covered = true;
                }
                if (isfast && !covered) committed = true;
            }

            unsigned cmask = __ballot_sync(full, committed);
            if (committed) {
                int cid = cid_base + __popc(cmask & ((1u << lane) - 1u));
                lenA[cid] = sz;
                staA[cid] = st;
                int bp = st + 32;
                unsigned long long m64 = ((1ull << sz) - 1ull) << (bp & 31);
                atomicOr(&asgw[bp >> 5], (unsigned)m64);
                unsigned hiw = (unsigned)(m64 >> 32);
                if (hiw) atomicOr(&asgw[(bp >> 5) + 1], hiw);
            }
            cid_base += __popc(cmask);
            __syncwarp(full);
        }
        if (lane == 0) *sh_ncl = cid_base;
    }
    __syncthreads();

    int ncl = *sh_ncl;
    for (int c = tid; c < T; c += 1024) {
        if (c >= ncl) { lenA[c] = 0; staA[c] = T; }
        key[c] = (float)(staA[c] * 4096 + c);
        ordA[c] = c;
    }
    __syncthreads();
    bitonic_sort_shared(key, ordA);

    for (int r = tid; r < T; r += 1024) {
        int c = ordA[r];
        g_clen[b * T + r] = lenA[c];
        g_cstart[b * T + r] = staA[c];
        if (lens_out) lens_out[b * T + r] = (float)lenA[c];
    }
}

// ---------------- 7) pool / fast-path copy -----------------------------------
__global__ void pool_kernel(const float* __restrict__ x, float* __restrict__ out,
                            float* lens_out) {
    int idx4 = blockIdx.x * blockDim.x + threadIdx.x;   // over B*D*T/4
    if (g_flag == 0) {
        // all singletons: embs = x exactly, lens = 1
        ((float4*)out)[idx4] = ((const float4*)x)[idx4];
        int base = idx4 * 4;
        int d = (base / T) % D;
        if (lens_out && d == 0) {
            int b = base / (T * D), t = base % T;
            *(float4*)&lens_out[b * T + t] = make_float4(1.f, 1.f, 1.f, 1.f);
        }
        return;
    }
    int base = idx4 * 4;
    int d = (base / T) % D;
    int b = base / (T * D);
#pragma unroll
    for (int q = 0; q < 4; q++) {
        int r = (base + q) % T;
        int len = g_clen[b * T + r];
        int st = g_cstart[b * T + r];
        float acc = 0.f;
        for (int k = 0; k < len; k++) acc += x[((size_t)b * D + d) * T + st + k];
        out[base + q] = len ? acc / (float)len : 0.f;
    }
}

// ---------------- launch ------------------------------------------------------
extern "C" void kernel_launch(void* const* d_in, const int* in_sizes, int n_in,
                              void* d_out, int out_size) {
    const float* x = (const float*)d_in[0];
    float* out = (float*)d_out;
    float* lens_out = (out_size >= (int)(B * D * T + B * T)) ? out + (size_t)B * D * T
                                                             : nullptr;

    const int CLU_SMEM = (6 * T + 67) * 4;
    cudaFuncSetAttribute(cluster_kernel,
                         cudaFuncAttributeMaxDynamicSharedMemorySize, CLU_SMEM);

    reset_flag_kernel<<<1, 1>>>();
    norm_kernel<<<(B * T) / 256, 256>>>(x);
    transpose_kernel<<<dim3(T / 32, D / 32, B), dim3(32, 8)>>>(x);
    gate_kernel<<<(B * T * 32) / 256, 256>>>();
    // fallback pipeline (each kernel early-exits when g_flag == 0)
    gemm_sim_kernel<<<dim3(T / 128, T / 128, B), 256>>>();
    rho_kernel<<<(B * T * 32) / 256, 256>>>();
    sort_rho_kernel<<<B, 1024>>>();
    segmin_kernel<<<dim3(4, 32, B), 256>>>();
    deltafix_kernel<<<(B * T) / 256, 256>>>();
    cluster_kernel<<<B, 1024, CLU_SMEM>>>(lens_out);
    pool_kernel<<<(B * D * T / 4) / 256, 256>>>(x, out, lens_out);
}

// round 10
// speedup vs baseline: 7.5573x; 1.0200x over previous
#include <cuda_runtime.h>
#include <cuda_bf16.h>
#include <math.h>

#define B 8
#define D 256
#define T 2048
#define KNN 10
#define BETA 0.2f
#define THR 0.7f

// ---------------- scratch (device globals; no allocations allowed) ----------
__device__ float g_invn[B * T];
__device__ __nv_bfloat16 g_xnb[B * T * D];     // [B,T,D] normalized bf16 (fallback)
__device__ __nv_bfloat16 g_simb[B * T * T];    // [B,T,T] bf16 (fallback)
__device__ float g_rho[B * T];
__device__ float g_s[B * T];
__device__ int   g_ord[B * T];
__device__ int   g_rank[B * T];
__device__ unsigned g_segmin[B * 32 * (T / 2)];
__device__ int   g_cstart[B * T];
__device__ int   g_clen[B * T];
__device__ int   g_flag;                       // 0 = all-singleton fast path

// ---------------- 1) row norms of x^T (+ flag reset) -------------------------
__global__ void norm_kernel(const float* __restrict__ x) {
    if (blockIdx.x == 0 && threadIdx.x == 0) g_flag = 0;
    int idx = blockIdx.x * blockDim.x + threadIdx.x;   // over B*T
    int b = idx / T, t = idx % T;
    const float* xb = x + (size_t)b * D * T;
    float s = 0.f;
#pragma unroll 8
    for (int d = 0; d < D; d++) {
        float v = xb[d * T + t];
        s += v * v;
    }
    g_invn[idx] = 1.0f / fmaxf(sqrtf(s), 1e-12f);
}

// ---------------- 2) gate: any band sim possibly > THR? ----------------------
// Growth needs sim - BETA*s > THR with s >= 0 (rho>0, delta in [0,1]), hence
// sim > THR on the +/-4 band (sim symmetric -> forward pairs cover both
// directions). Gate conservatively at sim > 0.68, i.e. dot > 0.36.
// Block: 8 warps; warp w covers d = w, w+8, ...; lanes = 32 consecutive t.
__global__ void __launch_bounds__(256) gate_kernel(const float* __restrict__ x) {
    const unsigned full = 0xffffffffu;
    int b = blockIdx.y, t0 = blockIdx.x * 32;
    int w = threadIdx.x >> 5, lane = threadIdx.x & 31;
    const float* xb = x + (size_t)b * D * T;

    float dt[4] = {0.f, 0.f, 0.f, 0.f};
    for (int d = w; d < D; d += 8) {
        const float* rowp = xb + (size_t)d * T + t0;
        float v = rowp[lane];
        float h = 0.f;
        if (lane < 4 && t0 + 32 + lane < T) h = rowp[32 + lane];
#pragma unroll
        for (int off = 1; off <= 4; off++) {
            float nb = __shfl_down_sync(full, v, off);
            float hb = __shfl_sync(full, h, (lane + off) & 31);
            float nv = (lane + off < 32) ? nb : hb;
            dt[off - 1] += v * nv;
        }
    }

    __shared__ float4 red[8][32];
    red[w][lane] = make_float4(dt[0], dt[1], dt[2], dt[3]);
    __syncthreads();

    if (w == 0) {
        float4 a = red[0][lane];
#pragma unroll
        for (int r = 1; r < 8; r++) {
            float4 p = red[r][lane];
            a.x += p.x; a.y += p.y; a.z += p.z; a.w += p.w;
        }
        int t = t0 + lane;
        float inv0 = g_invn[b * T + t];
        float d4[4] = {a.x, a.y, a.z, a.w};
        float mx = -1.f;
#pragma unroll
        for (int off = 1; off <= 4; off++) {
            if (t + off < T)
                mx = fmaxf(mx, d4[off - 1] * inv0 * g_invn[b * T + t + off]);
        }
        if (mx > 0.36f) atomicOr(&g_flag, 1);   // sim=(dot+1)/2 > 0.68
    }
}

// ---------------- 3) transpose + normalize -> bf16 (fallback only) -----------
__global__ void transpose_kernel(const float* __restrict__ x) {
    if (g_flag == 0) return;
    __shared__ float sh[32][33];
    int b = blockIdx.z;
    int t0 = blockIdx.x * 32, d0 = blockIdx.y * 32;
    int tx = threadIdx.x, ty = threadIdx.y;
    const float* xb = x + (size_t)b * D * T;
#pragma unroll
    for (int q = 0; q < 4; q++) {
        int d = d0 + ty + q * 8;
        sh[ty + q * 8][tx] = xb[d * T + t0 + tx];
    }
    __syncthreads();
#pragma unroll
    for (int q = 0; q < 4; q++) {
        int t = t0 + ty + q * 8;
        g_xnb[((size_t)b * T + t) * D + d0 + tx] =
            __float2bfloat16(sh[tx][ty + q * 8] * g_invn[b * T + t]);
    }
}

// ---------------- 4) sim GEMM (fallback only) --------------------------------
#define SKW 40

#define LOAD_STAGE(stage, k0)                                                        \
    {                                                                                \
        _Pragma("unroll")                                                            \
        for (int q = 0; q < 2; q++) {                                                \
            int idx = tid + q * 256;                                                 \
            int r = idx >> 2, c = idx & 3;                                           \
            const __nv_bfloat16* srcA = Ab + (size_t)(row0 + r) * D + (k0) + c * 8;  \
            unsigned dA = (unsigned)__cvta_generic_to_shared(                        \
                &As[stage][r * SKW + c * 8]);                                        \
            asm volatile("cp.async.cg.shared.global [%0], [%1], 16;\n"               \
                         :: "r"(dA), "l"(srcA));                                     \
            const __nv_bfloat16* srcB = Ab + (size_t)(col0 + r) * D + (k0) + c * 8;  \
            unsigned dB = (unsigned)__cvta_generic_to_shared(                        \
                &Bs[stage][r * SKW + c * 8]);                                        \
            asm volatile("cp.async.cg.shared.global [%0], [%1], 16;\n"               \
                         :: "r"(dB), "l"(srcB));                                     \
        }                                                                            \
        asm volatile("cp.async.commit_group;\n");                                    \
    }

__global__ void __launch_bounds__(256) gemm_sim_kernel() {
    if (g_flag == 0) return;
    int b = blockIdx.z;
    const __nv_bfloat16* Ab = g_xnb + (size_t)b * T * D;
    __nv_bfloat16* C = g_simb + (size_t)b * T * T;
    int row0 = blockIdx.y * 128, col0 = blockIdx.x * 128;

    __shared__ __nv_bfloat16 As[2][128 * SKW];
    __shared__ __nv_bfloat16 Bs[2][128 * SKW];

    int tid = threadIdx.x;
    int wid = tid >> 5, lane = tid & 31;
    int wm = wid >> 1, wn = wid & 1;
    int g = lane >> 2, tg = lane & 3;

    float acc[2][8][4];
#pragma unroll
    for (int mt = 0; mt < 2; mt++)
#pragma unroll
        for (int nt = 0; nt < 8; nt++)
#pragma unroll
            for (int e = 0; e < 4; e++) acc[mt][nt][e] = 0.f;

    LOAD_STAGE(0, 0)

    for (int kt = 0; kt < 8; kt++) {
        if (kt < 7) {
            LOAD_STAGE((kt + 1) & 1, (kt + 1) * 32)
            asm volatile("cp.async.wait_group 1;\n");
        } else {
            asm volatile("cp.async.wait_group 0;\n");
        }
        __syncthreads();
        int st = kt & 1;
#pragma unroll
        for (int kk = 0; kk < 32; kk += 16) {
            unsigned af[2][4], bf[8][2];
#pragma unroll
            for (int mt = 0; mt < 2; mt++) {
                const __nv_bfloat16* base = &As[st][(wm * 32 + mt * 16 + g) * SKW + kk + tg * 2];
                af[mt][0] = *(const unsigned*)(base);
                af[mt][1] = *(const unsigned*)(base + 8 * SKW);
                af[mt][2] = *(const unsigned*)(base + 8);
                af[mt][3] = *(const unsigned*)(base + 8 * SKW + 8);
            }
#pragma unroll
            for (int nt = 0; nt < 8; nt++) {
                const __nv_bfloat16* base = &Bs[st][(wn * 64 + nt * 8 + g) * SKW + kk + tg * 2];
                bf[nt][0] = *(const unsigned*)(base);
                bf[nt][1] = *(const unsigned*)(base + 8);
            }
#pragma unroll
            for (int mt = 0; mt < 2; mt++)
#pragma unroll
                for (int nt = 0; nt < 8; nt++) {
                    asm volatile(
                        "mma.sync.aligned.m16n8k16.row.col.f32.bf16.bf16.f32 "
                        "{%0,%1,%2,%3},{%4,%5,%6,%7},{%8,%9},{%0,%1,%2,%3};\n"
                        : "+f"(acc[mt][nt][0]), "+f"(acc[mt][nt][1]),
                          "+f"(acc[mt][nt][2]), "+f"(acc[mt][nt][3])
                        : "r"(af[mt][0]), "r"(af[mt][1]), "r"(af[mt][2]), "r"(af[mt][3]),
                          "r"(bf[nt][0]), "r"(bf[nt][1]));
                }
        }
        __syncthreads();
    }

#pragma unroll
    for (int mt = 0; mt < 2; mt++) {
        int r = row0 + wm * 32 + mt * 16 + g;
#pragma unroll
        for (int nt = 0; nt < 8; nt++) {
            int c = col0 + wn * 64 + nt * 8 + tg * 2;
            __nv_bfloat162 p0 = __floats2bfloat162_rn((acc[mt][nt][0] + 1.f) * 0.5f,
                                                      (acc[mt][nt][1] + 1.f) * 0.5f);
            __nv_bfloat162 p1 = __floats2bfloat162_rn((acc[mt][nt][2] + 1.f) * 0.5f,
                                                      (acc[mt][nt][3] + 1.f) * 0.5f);
            *(__nv_bfloat162*)&C[(size_t)r * T + c] = p0;
            *(__nv_bfloat162*)&C[(size_t)(r + 8) * T + c] = p1;
        }
    }
}

// ---------------- 5) rho (fallback only) -------------------------------------
__device__ __forceinline__ void ins11(float v, float* a) {
#pragma unroll
    for (int k = 0; k < 11; k++) {
        if (v > a[k]) { float tmp = a[k]; a[k] = v; v = tmp; }
    }
}

__global__ void rho_kernel() {
    if (g_flag == 0) return;
    int row = (blockIdx.x * blockDim.x + threadIdx.x) >> 5;
    int lane = threadIdx.x & 31;
    const uint4* r16 = (const uint4*)(g_simb + (size_t)row * T);

    float a[11];
#pragma unroll
    for (int k = 0; k < 11; k++) a[k] = -1e30f;

#pragma unroll
    for (int it = 0; it < 4; it++) {
        uint4 v0 = r16[lane + (2 * it) * 32];
        uint4 v1 = r16[lane + (2 * it + 1) * 32];
        __nv_bfloat162 p[8];
        p[0] = *(__nv_bfloat162*)&v0.x; p[1] = *(__nv_bfloat162*)&v0.y;
        p[2] = *(__nv_bfloat162*)&v0.z; p[3] = *(__nv_bfloat162*)&v0.w;
        p[4] = *(__nv_bfloat162*)&v1.x; p[5] = *(__nv_bfloat162*)&v1.y;
        p[6] = *(__nv_bfloat162*)&v1.z; p[7] = *(__nv_bfloat162*)&v1.w;
        __nv_bfloat162 m01 = __hmax2(p[0], p[1]), m23 = __hmax2(p[2], p[3]);
        __nv_bfloat162 m45 = __hmax2(p[4], p[5]), m67 = __hmax2(p[6], p[7]);
        __nv_bfloat162 m = __hmax2(__hmax2(m01, m23), __hmax2(m45, m67));
        float fm = fmaxf(__low2float(m), __high2float(m));
        if (fm > a[10]) {
#pragma unroll
            for (int q = 0; q < 8; q++) {
                float lo = __low2float(p[q]), hi = __high2float(p[q]);
                if (lo > a[10]) ins11(lo, a);
                if (hi > a[10]) ins11(hi, a);
            }
        }
    }
    float sum = 0.f;
#pragma unroll
    for (int r = 0; r < 11; r++) {
        float h = a[0], m = h;
#pragma unroll
        for (int o = 16; o > 0; o >>= 1) m = fmaxf(m, __shfl_xor_sync(0xffffffffu, m, o));
        unsigned msk = __ballot_sync(0xffffffffu, h == m);
        int winner = __ffs(msk) - 1;
        if (lane == winner) {
#pragma unroll
            for (int k = 0; k < 10; k++) a[k] = a[k + 1];
            a[10] = -1e30f;
        }
        if (r > 0) sum += m;
    }
    if (lane == 0) g_rho[row] = expf(-sum * (1.0f / KNN));
}

// ---------------- sorting helper ---------------------------------------------
__device__ __forceinline__ void bitonic_sort_shared(float* key, int* ord) {
    for (int k = 2; k <= T; k <<= 1) {
        for (int j = k >> 1; j > 0; j >>= 1) {
#pragma unroll 2
            for (int i = threadIdx.x; i < T; i += 1024) {
                int l = i ^ j;
                if (l > i) {
                    bool up = ((i & k) == 0);
                    float ki = key[i], kl = key[l];
                    int oi = ord[i], ol = ord[l];
                    bool iAfter = (ki > kl) || (ki == kl && oi > ol);
                    if (iAfter == up) {
                        key[i] = kl; key[l] = ki;
                        ord[i] = ol; ord[l] = oi;
                    }
                }
            }
            __syncthreads();
        }
    }
}

// ---------------- 6a) sort rows by rho desc (fallback only) ------------------
__global__ void __launch_bounds__(1024) sort_rho_kernel() {
    if (g_flag == 0) return;
    __shared__ float key[T];
    __shared__ int ord[T];
    int b = blockIdx.x, tid = threadIdx.x;
    for (int t = tid; t < T; t += 1024) { key[t] = -g_rho[b * T + t]; ord[t] = t; }
    __syncthreads();
    bitonic_sort_shared(key, ord);
    for (int k = tid; k < T; k += 1024) {
        int t = ord[k];
        g_ord[b * T + k] = t;
        g_rank[b * T + t] = k;
    }
}

// ---------------- 6b) segment mins (fallback only) ---------------------------
__global__ void __launch_bounds__(256) segmin_kernel() {
    if (g_flag == 0) return;
    __shared__ int rows[64];
    int b = blockIdx.z, seg = blockIdx.y, cc = blockIdx.x;
    int tid = threadIdx.x;
    if (tid < 64) rows[tid] = g_ord[b * T + seg * 64 + tid];
    __syncthreads();
    int cp = cc * 256 + tid;
    const __nv_bfloat16* S = g_simb + (size_t)b * T * T;
    __nv_bfloat162 run = __floats2bfloat162_rn(1e30f, 1e30f);
#pragma unroll 8
    for (int k = 0; k < 64; k++) {
        unsigned u = *(const unsigned*)(S + (size_t)rows[k] * T + cp * 2);
        run = __hmin2(run, *(__nv_bfloat162*)&u);
    }
    g_segmin[((size_t)b * 32 + seg) * (T / 2) + cp] = *(unsigned*)&run;
}

// ---------------- 6c) delta fix-up (fallback only) ---------------------------
__global__ void deltafix_kernel() {
    if (g_flag == 0) return;
    int idx = blockIdx.x * blockDim.x + threadIdx.x;
    int b = idx / T, i = idx % T;
    float rho_i = g_rho[idx];
    int r = g_rank[idx];
    int seg_i = r >> 6;

    float mn = 1e30f;
    const unsigned* segm = g_segmin + (size_t)b * 32 * (T / 2) + (i >> 1);
    for (int s = 0; s < seg_i; s++) {
        unsigned u = segm[(size_t)s * (T / 2)];
        __nv_bfloat162 p = *(__nv_bfloat162*)&u;
        float v = (i & 1) ? __high2float(p) : __low2float(p);
        mn = fminf(mn, v);
    }
    const int* ord = g_ord + b * T + (seg_i << 6);
    const __nv_bfloat16* S = g_simb + (size_t)b * T * T;
    int nown = r - (seg_i << 6);
    for (int k = 0; k < nown; k++) {
        int row = ord[k];
        if (g_rho[b * T + row] > rho_i)
            mn = fminf(mn, __bfloat162float(S[(size_t)row * T + i]));
    }
    float delta = (mn < 1e29f) ? mn
                               : __bfloat162float(S[(size_t)i * T + i]);
    g_s[idx] = rho_i * delta;
}

// ---------------- 7) clustering (fallback only) ------------------------------
__global__ void __launch_bounds__(1024) cluster_kernel(float* lens_out) {
    if (g_flag == 0) return;
    extern __shared__ char smem[];
    float* s_sh = (float*)smem;
    float* key  = s_sh + T;
    int* ordA = (int*)(key + T);
    int* lenA = ordA + T;
    int* staA = lenA + T;
    unsigned* thr_sh = (unsigned*)(staA + T);
    unsigned* asgw = thr_sh + T;
    int* sh_ncl = (int*)(asgw + 66);

    int b = blockIdx.x;
    int tid = threadIdx.x;

    for (int t = tid; t < T; t += 1024) s_sh[t] = g_s[b * T + t];
    for (int t = tid; t < 66; t += 1024) asgw[t] = 0u;
    __syncthreads();

    for (int t = tid; t < T; t += 1024) {
        unsigned m = 0;
        const __nv_bfloat16* row = g_simb + ((size_t)b * T + t) * T;
#pragma unroll
        for (int k = 0; k < 9; k++) {
            if (k == 4) continue;
            int j = t - 4 + k;
            if (j >= 0 && j < T &&
                (__bfloat162float(row[j]) - BETA * s_sh[j] > THR)) m |= 1u << k;
        }
        thr_sh[t] = m;
    }

    for (int t = tid; t < T; t += 1024) { key[t] = -s_sh[t]; ordA[t] = t; }
    __syncthreads();
    bitonic_sort_shared(key, ordA);

    if (tid < 32) {
        const unsigned full = 0xffffffffu;
        int lane = tid;
        int cid_base = 0;
        for (int p = 0; p < T; p += 32) {
            int seed = ordA[p + lane];
            unsigned thrm = thr_sh[seed];
            int bitpos = seed + 28;
            unsigned w0 = asgw[bitpos >> 5];
            unsigned w1 = asgw[(bitpos >> 5) + 1];
            unsigned A = (unsigned)(((((unsigned long long)w1 << 32) | w0)
                                     >> (bitpos & 31))) & 0x1FFu;
            bool pre = (A >> 4) & 1u;
            bool isfast = !pre && (thrm == 0u);
            bool isslow = !pre && (thrm != 0u);
            unsigned slowm = __ballot_sync(full, isslow);
            bool committed = false;
            int st = seed, sz = 1;

            if (slowm == 0u) {
                committed = isfast;
            } else {
                unsigned rem = slowm;
                while (rem) {
                    int i = __ffs(rem) - 1; rem &= rem - 1;
                    int wb_i = __shfl_sync(full, seed, i) - 4;
                    unsigned contrib = 0u;
                    int lo = -1, hi = -2;
                    if (committed) {
                        lo = max(st, wb_i); hi = min(st + sz - 1, wb_i + 8);
                    } else if (isfast && lane < i) {
                        lo = max(seed, wb_i); hi = min(seed, wb_i + 8);
                    }
                    if (lo <= hi) contrib = ((1u << (hi - lo + 1)) - 1u) << (lo - wb_i);
                    unsigned add = __reduce_or_sync(full, contrib);
                    if (lane == i) {
                        A |= add;
                        if (!((A >> 4) & 1u)) {
                            unsigned avail = thrm & ~A;
                            unsigned f4 = (avail >> 5) & 0xFu;
                            int f = min(__ffs(~f4) - 1, 3);
                            int size = 1 + f;
                            unsigned b4 = __brev(avail & 0xFu) >> 28;
                            int bb = min(__ffs(~b4) - 1, 4 - size);
                            st = seed - bb;
                            sz = size + bb;
                            committed = true;
                        }
                    }
                }
                unsigned cm = slowm;
                bool covered = false;
                while (cm) {
                    int j = __ffs(cm) - 1; cm &= cm - 1;
                    int stj = __shfl_sync(full, st, j);
                    int szj = __shfl_sync(full, sz, j);
                    int cmj = __shfl_sync(full, (int)committed, j);
                    if (isfast && j < lane && cmj && seed >= stj && seed < stj + szj)
                        covered = true;
                }
                if (isfast && !covered) committed = true;
            }

            unsigned cmask = __ballot_sync(full, committed);
            if (committed) {
                int cid = cid_base + __popc(cmask & ((1u << lane) - 1u));
                lenA[cid] = sz;
                staA[cid] = st;
                int bp = st + 32;
                unsigned long long m64 = ((1ull << sz) - 1ull) << (bp & 31);
                atomicOr(&asgw[bp >> 5], (unsigned)m64);
                unsigned hiw = (unsigned)(m64 >> 32);
                if (hiw) atomicOr(&asgw[(bp >> 5) + 1], hiw);
            }
            cid_base += __popc(cmask);
            __syncwarp(full);
        }
        if (lane == 0) *sh_ncl = cid_base;
    }
    __syncthreads();

    int ncl = *sh_ncl;
    for (int c = tid; c < T; c += 1024) {
        if (c >= ncl) { lenA[c] = 0; staA[c] = T; }
        key[c] = (float)(staA[c] * 4096 + c);
        ordA[c] = c;
    }
    __syncthreads();
    bitonic_sort_shared(key, ordA);

    for (int r = tid; r < T; r += 1024) {
        int c = ordA[r];
        g_clen[b * T + r] = lenA[c];
        g_cstart[b * T + r] = staA[c];
        if (lens_out) lens_out[b * T + r] = (float)lenA[c];
    }
}

// ---------------- 8) pool / fast-path copy -----------------------------------
__global__ void pool_kernel(const float* __restrict__ x, float* __restrict__ out,
                            float* lens_out) {
    int idx4 = blockIdx.x * blockDim.x + threadIdx.x;   // over B*D*T/4
    if (g_flag == 0) {
        // all singletons: embs = x exactly, lens = 1
        ((float4*)out)[idx4] = ((const float4*)x)[idx4];
        int base = idx4 * 4;
        int d = (base / T) % D;
        if (lens_out && d == 0) {
            int b = base / (T * D), t = base % T;
            *(float4*)&lens_out[b * T + t] = make_float4(1.f, 1.f, 1.f, 1.f);
        }
        return;
    }
    int base = idx4 * 4;
    int d = (base / T) % D;
    int b = base / (T * D);
#pragma unroll
    for (int q = 0; q < 4; q++) {
        int r = (base + q) % T;
        int len = g_clen[b * T + r];
        int st = g_cstart[b * T + r];
        float acc = 0.f;
        for (int k = 0; k < len; k++) acc += x[((size_t)b * D + d) * T + st + k];
        out[base + q] = len ? acc / (float)len : 0.f;
    }
}

// ---------------- launch ------------------------------------------------------
extern "C" void kernel_launch(void* const* d_in, const int* in_sizes, int n_in,
                              void* d_out, int out_size) {
    const float* x = (const float*)d_in[0];
    float* out = (float*)d_out;
    float* lens_out = (out_size >= (int)(B * D * T + B * T)) ? out + (size_t)B * D * T
                                                             : nullptr;

    const int CLU_SMEM = (6 * T + 67) * 4;
    cudaFuncSetAttribute(cluster_kernel,
                         cudaFuncAttributeMaxDynamicSharedMemorySize, CLU_SMEM);

    norm_kernel<<<(B * T) / 256, 256>>>(x);               // also resets g_flag
    gate_kernel<<<dim3(T / 32, B), 256>>>(x);
    // fallback pipeline (each kernel early-exits when g_flag == 0)
    transpose_kernel<<<dim3(T / 32, D / 32, B), dim3(32, 8)>>>(x);
    gemm_sim_kernel<<<dim3(T / 128, T / 128, B), 256>>>();
    rho_kernel<<<(B * T * 32) / 256, 256>>>();
    sort_rho_kernel<<<B, 1024>>>();
    segmin_kernel<<<dim3(4, 32, B), 256>>>();
    deltafix_kernel<<<(B * T) / 256, 256>>>();
    cluster_kernel<<<B, 1024, CLU_SMEM>>>(lens_out);
    pool_kernel<<<(B * D * T / 4) / 256, 256>>>(x, out, lens_out);
}

// round 13
// speedup vs baseline: 11.1188x; 1.4713x over previous
#include <cuda_runtime.h>
#include <cuda_bf16.h>
#include <math.h>

#define B 8
#define D 256
#define T 2048
#define KNN 10
#define BETA 0.2f
#define THR 0.7f

// ---------------- scratch (device globals; no allocations allowed) ----------
__device__ float g_invn[B * T];
__device__ __nv_bfloat16 g_xnb[B * T * D];     // [B,T,D] normalized bf16 (fallback)
__device__ __nv_bfloat16 g_simb[B * T * T];    // [B,T,T] bf16 (fallback)
__device__ float g_rho[B * T];
__device__ float g_s[B * T];
__device__ int   g_ord[B * T];
__device__ int   g_rank[B * T];
__device__ unsigned g_segmin[B * 32 * (T / 2)];
__device__ int   g_cstart[B * T];
__device__ int   g_clen[B * T];
// 0 = all-singleton fast path. Statically zero; monotonic: set only when the
// gate trips, and for such an input it trips identically on every replay.
__device__ int   g_flag;

// ---------------- 1) gate + norms --------------------------------------------
// Growth needs sim - BETA*s > THR with s >= 0 (rho>0, delta in [0,1]), hence
// sim > THR on the +/-4 band (sim symmetric -> forward pairs cover both
// directions). Gate conservatively at sim > 0.68, i.e. normalized dot > 0.36.
// Also computes g_invn (row inverse norms) for the fallback path.
// Block: 8 warps; warp w covers d = w, w+8, ...; lanes = 32 consecutive t.
__global__ void __launch_bounds__(256) gate_kernel(const float* __restrict__ x) {
    const unsigned full = 0xffffffffu;
    int b = blockIdx.y, t0 = blockIdx.x * 32;
    int w = threadIdx.x >> 5, lane = threadIdx.x & 31;
    const float* xb = x + (size_t)b * D * T;

    float dt[4] = {0.f, 0.f, 0.f, 0.f};
    float nrm = 0.f, hn = 0.f;
    for (int d = w; d < D; d += 8) {
        const float* rowp = xb + (size_t)d * T + t0;
        float v = rowp[lane];
        float h = 0.f;
        if (lane < 4 && t0 + 32 + lane < T) h = rowp[32 + lane];
        nrm += v * v;
        hn  += h * h;
#pragma unroll
        for (int off = 1; off <= 4; off++) {
            float nb = __shfl_down_sync(full, v, off);
            float hb = __shfl_sync(full, h, (lane + off) & 31);
            float nv = (lane + off < 32) ? nb : hb;
            dt[off - 1] += v * nv;
        }
    }

    __shared__ float red[8][32][6];
    red[w][lane][0] = dt[0]; red[w][lane][1] = dt[1];
    red[w][lane][2] = dt[2]; red[w][lane][3] = dt[3];
    red[w][lane][4] = nrm;   red[w][lane][5] = hn;
    __syncthreads();

    if (w == 0) {
        float a0 = red[0][lane][0], a1 = red[0][lane][1];
        float a2 = red[0][lane][2], a3 = red[0][lane][3];
        float an = red[0][lane][4], ah = red[0][lane][5];
#pragma unroll
        for (int r = 1; r < 8; r++) {
            a0 += red[r][lane][0]; a1 += red[r][lane][1];
            a2 += red[r][lane][2]; a3 += red[r][lane][3];
            an += red[r][lane][4]; ah += red[r][lane][5];
        }
        int t = t0 + lane;
        float inv0 = 1.f / fmaxf(sqrtf(an), 1e-12f);
        g_invn[b * T + t] = inv0;                       // fallback needs this
        float invh = 1.f / fmaxf(sqrtf(ah), 1e-12f);    // valid on lanes 0..3
        float d4[4] = {a0, a1, a2, a3};
        float mx = -1.f;
#pragma unroll
        for (int off = 1; off <= 4; off++) {
            float invA = __shfl_sync(full, inv0, (lane + off) & 31);
            float invB = __shfl_sync(full, invh, (lane + off) & 31);
            float invo = (lane + off < 32) ? invA : invB;
            if (t + off < T) mx = fmaxf(mx, d4[off - 1] * inv0 * invo);
        }
        if (mx > 0.36f) atomicOr(&g_flag, 1);   // sim=(dot+1)/2 > 0.68
    }
}

// ---------------- 2) transpose + normalize -> bf16 (fallback, grid-stride) ---
__global__ void transpose_kernel(const float* __restrict__ x) {
    if (g_flag == 0) return;
    __shared__ float sh[32][33];
    int tx = threadIdx.x, ty = threadIdx.y;
    for (int tile = blockIdx.x; tile < 64 * 8 * B; tile += 128) {
        int t0 = (tile & 63) * 32;
        int d0 = ((tile >> 6) & 7) * 32;
        int b = tile >> 9;
        const float* xb = x + (size_t)b * D * T;
        __syncthreads();
#pragma unroll
        for (int q = 0; q < 4; q++) {
            int d = d0 + ty + q * 8;
            sh[ty + q * 8][tx] = xb[d * T + t0 + tx];
        }
        __syncthreads();
#pragma unroll
        for (int q = 0; q < 4; q++) {
            int t = t0 + ty + q * 8;
            g_xnb[((size_t)b * T + t) * D + d0 + tx] =
                __float2bfloat16(sh[tx][ty + q * 8] * g_invn[b * T + t]);
        }
    }
}

// ---------------- 3) sim GEMM (fallback, grid-stride) ------------------------
#define SKW 40

#define LOAD_STAGE(stage, k0)                                                        \
    {                                                                                \
        _Pragma("unroll")                                                            \
        for (int q = 0; q < 2; q++) {                                                \
            int idx = tid + q * 256;                                                 \
            int r = idx >> 2, c = idx & 3;                                           \
            const __nv_bfloat16* srcA = Ab + (size_t)(row0 + r) * D + (k0) + c * 8;  \
            unsigned dA = (unsigned)__cvta_generic_to_shared(                        \
                &As[stage][r * SKW + c * 8]);                                        \
            asm volatile("cp.async.cg.shared.global [%0], [%1], 16;\n"               \
                         :: "r"(dA), "l"(srcA));                                     \
            const __nv_bfloat16* srcB = Ab + (size_t)(col0 + r) * D + (k0) + c * 8;  \
            unsigned dB = (unsigned)__cvta_generic_to_shared(                        \
                &Bs[stage][r * SKW + c * 8]);                                        \
            asm volatile("cp.async.cg.shared.global [%0], [%1], 16;\n"               \
                         :: "r"(dB), "l"(srcB));                                     \
        }                                                                            \
        asm volatile("cp.async.commit_group;\n");                                    \
    }

__global__ void __launch_bounds__(256) gemm_sim_kernel() {
    if (g_flag == 0) return;
    __shared__ __nv_bfloat16 As[2][128 * SKW];
    __shared__ __nv_bfloat16 Bs[2][128 * SKW];

    int tid = threadIdx.x;
    int wid = tid >> 5, lane = tid & 31;
    int wm = wid >> 1, wn = wid & 1;
    int g = lane >> 2, tg = lane & 3;

    for (int tile = blockIdx.x; tile < 2048; tile += 256) {
        int b = tile >> 8;
        int row0 = ((tile >> 4) & 15) * 128;
        int col0 = (tile & 15) * 128;
        const __nv_bfloat16* Ab = g_xnb + (size_t)b * T * D;
        __nv_bfloat16* C = g_simb + (size_t)b * T * T;

        float acc[2][8][4];
#pragma unroll
        for (int mt = 0; mt < 2; mt++)
#pragma unroll
            for (int nt = 0; nt < 8; nt++)
#pragma unroll
                for (int e = 0; e < 4; e++) acc[mt][nt][e] = 0.f;

        __syncthreads();
        LOAD_STAGE(0, 0)

        for (int kt = 0; kt < 8; kt++) {
            if (kt < 7) {
                LOAD_STAGE((kt + 1) & 1, (kt + 1) * 32)
                asm volatile("cp.async.wait_group 1;\n");
            } else {
                asm volatile("cp.async.wait_group 0;\n");
            }
            __syncthreads();
            int st = kt & 1;
#pragma unroll
            for (int kk = 0; kk < 32; kk += 16) {
                unsigned af[2][4], bf[8][2];
#pragma unroll
                for (int mt = 0; mt < 2; mt++) {
                    const __nv_bfloat16* base =
                        &As[st][(wm * 32 + mt * 16 + g) * SKW + kk + tg * 2];
                    af[mt][0] = *(const unsigned*)(base);
                    af[mt][1] = *(const unsigned*)(base + 8 * SKW);
                    af[mt][2] = *(const unsigned*)(base + 8);
                    af[mt][3] = *(const unsigned*)(base + 8 * SKW + 8);
                }
#pragma unroll
                for (int nt = 0; nt < 8; nt++) {
                    const __nv_bfloat16* base =
                        &Bs[st][(wn * 64 + nt * 8 + g) * SKW + kk + tg * 2];
                    bf[nt][0] = *(const unsigned*)(base);
                    bf[nt][1] = *(const unsigned*)(base + 8);
                }
#pragma unroll
                for (int mt = 0; mt < 2; mt++)
#pragma unroll
                    for (int nt = 0; nt < 8; nt++) {
                        asm volatile(
                            "mma.sync.aligned.m16n8k16.row.col.f32.bf16.bf16.f32 "
                            "{%0,%1,%2,%3},{%4,%5,%6,%7},{%8,%9},{%0,%1,%2,%3};\n"
                            : "+f"(acc[mt][nt][0]), "+f"(acc[mt][nt][1]),
                              "+f"(acc[mt][nt][2]), "+f"(acc[mt][nt][3])
                            : "r"(af[mt][0]), "r"(af[mt][1]),
                              "r"(af[mt][2]), "r"(af[mt][3]),
                              "r"(bf[nt][0]), "r"(bf[nt][1]));
                    }
            }
            __syncthreads();
        }

#pragma unroll
        for (int mt = 0; mt < 2; mt++) {
            int r = row0 + wm * 32 + mt * 16 + g;
#pragma unroll
            for (int nt = 0; nt < 8; nt++) {
                int c = col0 + wn * 64 + nt * 8 + tg * 2;
                __nv_bfloat162 p0 = __floats2bfloat162_rn((acc[mt][nt][0] + 1.f) * 0.5f,
                                                          (acc[mt][nt][1] + 1.f) * 0.5f);
                __nv_bfloat162 p1 = __floats2bfloat162_rn((acc[mt][nt][2] + 1.f) * 0.5f,
                                                          (acc[mt][nt][3] + 1.f) * 0.5f);
                *(__nv_bfloat162*)&C[(size_t)r * T + c] = p0;
                *(__nv_bfloat162*)&C[(size_t)(r + 8) * T + c] = p1;
            }
        }
    }
}

// ---------------- 4) rho (fallback, grid-stride) -----------------------------
__device__ __forceinline__ void ins11(float v, float* a) {
#pragma unroll
    for (int k = 0; k < 11; k++) {
        if (v > a[k]) { float tmp = a[k]; a[k] = v; v = tmp; }
    }
}

__global__ void rho_kernel() {
    if (g_flag == 0) return;
    int lane = threadIdx.x & 31;
    for (int it = 0; it < 8; it++) {
        int row = ((blockIdx.x * blockDim.x + threadIdx.x) >> 5) + it * 2048;
        const uint4* r16 = (const uint4*)(g_simb + (size_t)row * T);

        float a[11];
#pragma unroll
        for (int k = 0; k < 11; k++) a[k] = -1e30f;

#pragma unroll
        for (int jt = 0; jt < 4; jt++) {
            uint4 v0 = r16[lane + (2 * jt) * 32];
            uint4 v1 = r16[lane + (2 * jt + 1) * 32];
            __nv_bfloat162 p[8];
            p[0] = *(__nv_bfloat162*)&v0.x; p[1] = *(__nv_bfloat162*)&v0.y;
            p[2] = *(__nv_bfloat162*)&v0.z; p[3] = *(__nv_bfloat162*)&v0.w;
            p[4] = *(__nv_bfloat162*)&v1.x; p[5] = *(__nv_bfloat162*)&v1.y;
            p[6] = *(__nv_bfloat162*)&v1.z; p[7] = *(__nv_bfloat162*)&v1.w;
            __nv_bfloat162 m01 = __hmax2(p[0], p[1]), m23 = __hmax2(p[2], p[3]);
            __nv_bfloat162 m45 = __hmax2(p[4], p[5]), m67 = __hmax2(p[6], p[7]);
            __nv_bfloat162 m = __hmax2(__hmax2(m01, m23), __hmax2(m45, m67));
            float fm = fmaxf(__low2float(m), __high2float(m));
            if (fm > a[10]) {
#pragma unroll
                for (int q = 0; q < 8; q++) {
                    float lo = __low2float(p[q]), hi = __high2float(p[q]);
                    if (lo > a[10]) ins11(lo, a);
                    if (hi > a[10]) ins11(hi, a);
                }
            }
        }
        float sum = 0.f;
#pragma unroll
        for (int r = 0; r < 11; r++) {
            float h = a[0], m = h;
#pragma unroll
            for (int o = 16; o > 0; o >>= 1)
                m = fmaxf(m, __shfl_xor_sync(0xffffffffu, m, o));
            unsigned msk = __ballot_sync(0xffffffffu, h == m);
            int winner = __ffs(msk) - 1;
            if (lane == winner) {
#pragma unroll
                for (int k = 0; k < 10; k++) a[k] = a[k + 1];
                a[10] = -1e30f;
            }
            if (r > 0) sum += m;
        }
        if (lane == 0) g_rho[row] = expf(-sum * (1.0f / KNN));
    }
}

// ---------------- sorting helper ---------------------------------------------
__device__ __forceinline__ void bitonic_sort_shared(float* key, int* ord) {
    for (int k = 2; k <= T; k <<= 1) {
        for (int j = k >> 1; j > 0; j >>= 1) {
#pragma unroll 2
            for (int i = threadIdx.x; i < T; i += 1024) {
                int l = i ^ j;
                if (l > i) {
                    bool up = ((i & k) == 0);
                    float ki = key[i], kl = key[l];
                    int oi = ord[i], ol = ord[l];
                    bool iAfter = (ki > kl) || (ki == kl && oi > ol);
                    if (iAfter == up) {
                        key[i] = kl; key[l] = ki;
                        ord[i] = ol; ord[l] = oi;
                    }
                }
            }
            __syncthreads();
        }
    }
}

// ---------------- 5a) sort rows by rho desc (fallback only) ------------------
__global__ void __launch_bounds__(1024) sort_rho_kernel() {
    if (g_flag == 0) return;
    __shared__ float key[T];
    __shared__ int ord[T];
    int b = blockIdx.x, tid = threadIdx.x;
    for (int t = tid; t < T; t += 1024) { key[t] = -g_rho[b * T + t]; ord[t] = t; }
    __syncthreads();
    bitonic_sort_shared(key, ord);
    for (int k = tid; k < T; k += 1024) {
        int t = ord[k];
        g_ord[b * T + k] = t;
        g_rank[b * T + t] = k;
    }
}

// ---------------- 5b) segment mins (fallback, grid-stride) -------------------
__global__ void __launch_bounds__(256) segmin_kernel() {
    if (g_flag == 0) return;
    __shared__ int rows[64];
    int tid = threadIdx.x;
    for (int it = 0; it < 4; it++) {
        int id = blockIdx.x + it * 256;
        int cc = id & 3, seg = (id >> 2) & 31, b = id >> 7;
        __syncthreads();
        if (tid < 64) rows[tid] = g_ord[b * T + seg * 64 + tid];
        __syncthreads();
        int cp = cc * 256 + tid;
        const __nv_bfloat16* S = g_simb + (size_t)b * T * T;
        __nv_bfloat162 run = __floats2bfloat162_rn(1e30f, 1e30f);
#pragma unroll 8
        for (int k = 0; k < 64; k++) {
            unsigned u = *(const unsigned*)(S + (size_t)rows[k] * T + cp * 2);
            run = __hmin2(run, *(__nv_bfloat162*)&u);
        }
        g_segmin[((size_t)b * 32 + seg) * (T / 2) + cp] = *(unsigned*)&run;
    }
}

// ---------------- 5c) delta fix-up (fallback only) ---------------------------
__global__ void deltafix_kernel() {
    if (g_flag == 0) return;
    int idx = blockIdx.x * blockDim.x + threadIdx.x;
    int b = idx / T, i = idx % T;
    float rho_i = g_rho[idx];
    int r = g_rank[idx];
    int seg_i = r >> 6;

    float mn = 1e30f;
    const unsigned* segm = g_segmin + (size_t)b * 32 * (T / 2) + (i >> 1);
    for (int s = 0; s < seg_i; s++) {
        unsigned u = segm[(size_t)s * (T / 2)];
        __nv_bfloat162 p = *(__nv_bfloat162*)&u;
        float v = (i & 1) ? __high2float(p) : __low2float(p);
        mn = fminf(mn, v);
    }
    const int* ord = g_ord + b * T + (seg_i << 6);
    const __nv_bfloat16* S = g_simb + (size_t)b * T * T;
    int nown = r - (seg_i << 6);
    for (int k = 0; k < nown; k++) {
        int row = ord[k];
        if (g_rho[b * T + row] > rho_i)
            mn = fminf(mn, __bfloat162float(S[(size_t)row * T + i]));
    }
    float delta = (mn < 1e29f) ? mn
                               : __bfloat162float(S[(size_t)i * T + i]);
    g_s[idx] = rho_i * delta;
}

// ---------------- 6) clustering (fallback only) ------------------------------
__global__ void __launch_bounds__(1024) cluster_kernel(float* lens_out) {
    if (g_flag == 0) return;
    extern __shared__ char smem[];
    float* s_sh = (float*)smem;
    float* key  = s_sh + T;
    int* ordA = (int*)(key + T);
    int* lenA = ordA + T;
    int* staA = lenA + T;
    unsigned* thr_sh = (unsigned*)(staA + T);
    unsigned* asgw = thr_sh + T;
    int* sh_ncl = (int*)(asgw + 66);

    int b = blockIdx.x;
    int tid = threadIdx.x;

    for (int t = tid; t < T; t += 1024) s_sh[t] = g_s[b * T + t];
    for (int t = tid; t < 66; t += 1024) asgw[t] = 0u;
    __syncthreads();

    for (int t = tid; t < T; t += 1024) {
        unsigned m = 0;
        const __nv_bfloat16* row = g_simb + ((size_t)b * T + t) * T;
#pragma unroll
        for (int k = 0; k < 9; k++) {
            if (k == 4) continue;
            int j = t - 4 + k;
            if (j >= 0 && j < T &&
                (__bfloat162float(row[j]) - BETA * s_sh[j] > THR)) m |= 1u << k;
        }
        thr_sh[t] = m;
    }

    for (int t = tid; t < T; t += 1024) { key[t] = -s_sh[t]; ordA[t] = t; }
    __syncthreads();
    bitonic_sort_shared(key, ordA);

    if (tid < 32) {
        const unsigned full = 0xffffffffu;
        int lane = tid;
        int cid_base = 0;
        for (int p = 0; p < T; p += 32) {
            int seed = ordA[p + lane];
            unsigned thrm = thr_sh[seed];
            int bitpos = seed + 28;
            unsigned w0 = asgw[bitpos >> 5];
            unsigned w1 = asgw[(bitpos >> 5) + 1];
            unsigned A = (unsigned)(((((unsigned long long)w1 << 32) | w0)
                                     >> (bitpos & 31))) & 0x1FFu;
            bool pre = (A >> 4) & 1u;
            bool isfast = !pre && (thrm == 0u);
            bool isslow = !pre && (thrm != 0u);
            unsigned slowm = __ballot_sync(full, isslow);
            bool committed = false;
            int st = seed, sz = 1;

            if (slowm == 0u) {
                committed = isfast;
            } else {
                unsigned rem = slowm;
                while (rem) {
                    int i = __ffs(rem) - 1; rem &= rem - 1;
                    int wb_i = __shfl_sync(full, seed, i) - 4;
                    unsigned contrib = 0u;
                    int lo = -1, hi = -2;
                    if (committed) {
                        lo = max(st, wb_i); hi = min(st + sz - 1, wb_i + 8);
                    } else if (isfast && lane < i) {
                        lo = max(seed, wb_i); hi = min(seed, wb_i + 8);
                    }
                    if (lo <= hi) contrib = ((1u << (hi - lo + 1)) - 1u) << (lo - wb_i);
                    unsigned add = __reduce_or_sync(full, contrib);
                    if (lane == i) {
                        A |= add;
                        if (!((A >> 4) & 1u)) {
                            unsigned avail = thrm & ~A;
                            unsigned f4 = (avail >> 5) & 0xFu;
                            int f = min(__ffs(~f4) - 1, 3);
                            int size = 1 + f;
                            unsigned b4 = __brev(avail & 0xFu) >> 28;
                            int bb = min(__ffs(~b4) - 1, 4 - size);
                            st = seed - bb;
                            sz = size + bb;
                            committed = true;
                        }
                    }
                }
                unsigned cm = slowm;
                bool covered = false;
                while (cm) {
                    int j = __ffs(cm) - 1; cm &= cm - 1;
                    int stj = __shfl_sync(full, st, j);
                    int szj = __shfl_sync(full, sz, j);
                    int cmj = __shfl_sync(full, (int)committed, j);
                    if (isfast && j < lane && cmj && seed >= stj && seed < stj + szj)
                        covered = true;
                }
                if (isfast && !covered) committed = true;
            }

            unsigned cmask = __ballot_sync(full, committed);
            if (committed) {
                int cid = cid_base + __popc(cmask & ((1u << lane) - 1u));
                lenA[cid] = sz;
                staA[cid] = st;
                int bp = st + 32;
                unsigned long long m64 = ((1ull << sz) - 1ull) << (bp & 31);
                atomicOr(&asgw[bp >> 5], (unsigned)m64);
                unsigned hiw = (unsigned)(m64 >> 32);
                if (hiw) atomicOr(&asgw[(bp >> 5) + 1], hiw);
            }
            cid_base += __popc(cmask);
            __syncwarp(full);
        }
        if (lane == 0) *sh_ncl = cid_base;
    }
    __syncthreads();

    int ncl = *sh_ncl;
    for (int c = tid; c < T; c += 1024) {
        if (c >= ncl) { lenA[c] = 0; staA[c] = T; }
        key[c] = (float)(staA[c] * 4096 + c);
        ordA[c] = c;
    }
    __syncthreads();
    bitonic_sort_shared(key, ordA);

    for (int r = tid; r < T; r += 1024) {
        int c = ordA[r];
        g_clen[b * T + r] = lenA[c];
        g_cstart[b * T + r] = staA[c];
        if (lens_out) lens_out[b * T + r] = (float)lenA[c];
    }
}

// ---------------- 7) pool / fast-path copy (grid-stride) ---------------------
__global__ void pool_kernel(const float* __restrict__ x, float* __restrict__ out,
                            float* lens_out) {
    int flag = g_flag;
    int stride = gridDim.x * blockDim.x;
    for (int idx4 = blockIdx.x * blockDim.x + threadIdx.x;
         idx4 < B * D * T / 4; idx4 += stride) {
        if (flag == 0) {
            // all singletons: embs = x exactly, lens = 1
            ((float4*)out)[idx4] = ((const float4*)x)[idx4];
            int base = idx4 * 4;
            int d = (base / T) % D;
            if (lens_out && d == 0) {
                int b = base / (T * D), t = base % T;
                *(float4*)&lens_out[b * T + t] = make_float4(1.f, 1.f, 1.f, 1.f);
            }
            continue;
        }
        int base = idx4 * 4;
        int d = (base / T) % D;
        int b = base / (T * D);
#pragma unroll
        for (int q = 0; q < 4; q++) {
            int r = (base + q) % T;
            int len = g_clen[b * T + r];
            int st = g_cstart[b * T + r];
            float acc = 0.f;
            for (int k = 0; k < len; k++) acc += x[((size_t)b * D + d) * T + st + k];
            out[base + q] = len ? acc / (float)len : 0.f;
        }
    }
}

// ---------------- launch ------------------------------------------------------
extern "C" void kernel_launch(void* const* d_in, const int* in_sizes, int n_in,
                              void* d_out, int out_size) {
    const float* x = (const float*)d_in[0];
    float* out = (float*)d_out;
    float* lens_out = (out_size >= (int)(B * D * T + B * T)) ? out + (size_t)B * D * T
                                                             : nullptr;

    const int CLU_SMEM = (6 * T + 67) * 4;
    cudaFuncSetAttribute(cluster_kernel,
                         cudaFuncAttributeMaxDynamicSharedMemorySize, CLU_SMEM);

    gate_kernel<<<dim3(T / 32, B), 256>>>(x);   // gate + norms (writes g_invn)
    // fallback pipeline (each kernel early-exits when g_flag == 0)
    transpose_kernel<<<128, dim3(32, 8)>>>(x);
    gemm_sim_kernel<<<256, 256>>>();
    rho_kernel<<<256, 256>>>();
    sort_rho_kernel<<<B, 1024>>>();
    segmin_kernel<<<256, 256>>>();
    deltafix_kernel<<<64, 256>>>();
    cluster_kernel<<<B, 1024, CLU_SMEM>>>(lens_out);
    pool_kernel<<<1024, 256>>>(x, out, lens_out);
}

// round 14
// speedup vs baseline: 19.3467x; 1.7400x over previous
#include <cuda_runtime.h>
#include <cuda_bf16.h>
#include <math.h>

#define B 8
#define D 256
#define T 2048
#define KNN 10
#define BETA 0.2f
#define THR 0.7f

// ---------------- scratch (device globals; no allocations allowed) ----------
__device__ float g_invn[B * T];
__device__ __nv_bfloat16 g_xnb[B * T * D];     // fallback only
__device__ __nv_bfloat16 g_simb[B * T * T];    // fallback only
__device__ float g_rho[B * T];
__device__ float g_s[B * T];
__device__ int   g_ord[B * T];
__device__ int   g_rank[B * T];
__device__ unsigned g_segmin[B * 32 * (T / 2)];
__device__ int   g_cstart[B * T];
__device__ int   g_clen[B * T];
// 0 = all-singleton fast path. Statically zero; monotonic: set only when the
// gate trips, and for such an input it trips identically on every replay.
__device__ int   g_flag;

// ---------------- 1) gate + norms + fast-path copy ---------------------------
// Growth needs sim - BETA*s > THR with s >= 0 (rho>0, delta in [0,1]), hence
// sim > THR on the +/-4 band. Gate conservatively at sim > 0.68 (dot > 0.36).
// Writes out = x and lens = 1 unconditionally (exact on the fast path); the
// guarded fallback overwrites both when the gate trips.
__global__ void __launch_bounds__(256) gate_kernel(const float* __restrict__ x,
                                                   float* __restrict__ out,
                                                   float* lens_out) {
    const unsigned full = 0xffffffffu;
    int b = blockIdx.y, t0 = blockIdx.x * 32;
    int w = threadIdx.x >> 5, lane = threadIdx.x & 31;
    const float* xb = x + (size_t)b * D * T;
    float* ob = out + (size_t)b * D * T;

    float dt[4] = {0.f, 0.f, 0.f, 0.f};
    float nrm = 0.f, hn = 0.f;
    for (int d = w; d < D; d += 8) {
        const float* rowp = xb + (size_t)d * T + t0;
        float v = rowp[lane];
        ob[(size_t)d * T + t0 + lane] = v;          // fast-path copy (out = x)
        float h = 0.f;
        if (lane < 4 && t0 + 32 + lane < T) h = rowp[32 + lane];
        nrm += v * v;
        hn  += h * h;
#pragma unroll
        for (int off = 1; off <= 4; off++) {
            float nb = __shfl_down_sync(full, v, off);
            float hb = __shfl_sync(full, h, (lane + off) & 31);
            float nv = (lane + off < 32) ? nb : hb;
            dt[off - 1] += v * nv;
        }
    }

    __shared__ float red[8][32][6];
    red[w][lane][0] = dt[0]; red[w][lane][1] = dt[1];
    red[w][lane][2] = dt[2]; red[w][lane][3] = dt[3];
    red[w][lane][4] = nrm;   red[w][lane][5] = hn;
    __syncthreads();

    if (w == 0) {
        float a0 = red[0][lane][0], a1 = red[0][lane][1];
        float a2 = red[0][lane][2], a3 = red[0][lane][3];
        float an = red[0][lane][4], ah = red[0][lane][5];
#pragma unroll
        for (int r = 1; r < 8; r++) {
            a0 += red[r][lane][0]; a1 += red[r][lane][1];
            a2 += red[r][lane][2]; a3 += red[r][lane][3];
            an += red[r][lane][4]; ah += red[r][lane][5];
        }
        int t = t0 + lane;
        float inv0 = 1.f / fmaxf(sqrtf(an), 1e-12f);
        g_invn[b * T + t] = inv0;                       // fallback needs this
        if (lens_out) lens_out[b * T + t] = 1.0f;       // fast-path lens
        float invh = 1.f / fmaxf(sqrtf(ah), 1e-12f);    // valid on lanes 0..3
        float d4[4] = {a0, a1, a2, a3};
        float mx = -1.f;
#pragma unroll
        for (int off = 1; off <= 4; off++) {
            float invA = __shfl_sync(full, inv0, (lane + off) & 31);
            float invB = __shfl_sync(full, invh, (lane + off) & 31);
            float invo = (lane + off < 32) ? invA : invB;
            if (t + off < T) mx = fmaxf(mx, d4[off - 1] * inv0 * invo);
        }
        if (mx > 0.36f) atomicOr(&g_flag, 1);   // sim=(dot+1)/2 > 0.68
    }
}

// ---------------- helpers (fallback) -----------------------------------------
__device__ __forceinline__ void bitonic_sort_shared(float* key, int* ord) {
    for (int k = 2; k <= T; k <<= 1) {
        for (int j = k >> 1; j > 0; j >>= 1) {
            for (int i = threadIdx.x; i < T; i += 1024) {
                int l = i ^ j;
                if (l > i) {
                    bool up = ((i & k) == 0);
                    float ki = key[i], kl = key[l];
                    int oi = ord[i], ol = ord[l];
                    bool iAfter = (ki > kl) || (ki == kl && oi > ol);
                    if (iAfter == up) {
                        key[i] = kl; key[l] = ki;
                        ord[i] = ol; ord[l] = oi;
                    }
                }
            }
            __syncthreads();
        }
    }
}

__device__ __forceinline__ void ins11(float v, float* a) {
#pragma unroll
    for (int k = 0; k < 11; k++) {
        if (v > a[k]) { float tmp = a[k]; a[k] = v; v = tmp; }
    }
}

// ---------------- 2) fallback mega-kernel (one block per batch) --------------
// Every stage of the reference pipeline is batch-local, so one 1024-thread
// block per batch runs the whole fallback with __syncthreads() between stages.
// Never executes for gate-clean inputs; correctness (not speed) is its job.
__global__ void __launch_bounds__(1024) fallback_kernel(const float* __restrict__ x,
                                                        float* __restrict__ out,
                                                        float* lens_out) {
    if (g_flag == 0) return;
    extern __shared__ char smem[];
    int b = blockIdx.x;
    int tid = threadIdx.x;
    int wid = tid >> 5, lane = tid & 31;
    const unsigned full = 0xffffffffu;

    // ---- S1: transpose + normalize -> xnb[b] ----
    for (int idx = tid; idx < T * D; idx += 1024) {
        int t = idx >> 8, d = idx & 255;               // D = 256
        g_xnb[((size_t)b * T + t) * D + d] =
            __float2bfloat16(x[(size_t)b * D * T + (size_t)d * T + t] * g_invn[b * T + t]);
    }
    __syncthreads();

    // ---- S2: sim = (xn @ xn^T + 1)/2, bf16 store (SIMT; fallback-speed) ----
    {
        const __nv_bfloat16* Ab = g_xnb + (size_t)b * T * D;
        __nv_bfloat16* C = g_simb + (size_t)b * T * T;
        for (int ij = tid; ij < T * T; ij += 1024) {
            int i = ij >> 11, j = ij & (T - 1);
            const __nv_bfloat162* ar = (const __nv_bfloat162*)(Ab + (size_t)i * D);
            const __nv_bfloat162* br = (const __nv_bfloat162*)(Ab + (size_t)j * D);
            float acc = 0.f;
#pragma unroll 8
            for (int k = 0; k < D / 2; k++) {
                float2 fa = __bfloat1622float2(ar[k]);
                float2 fb = __bfloat1622float2(br[k]);
                acc += fa.x * fb.x + fa.y * fb.y;
            }
            C[(size_t)i * T + j] = __float2bfloat16((acc + 1.f) * 0.5f);
        }
    }
    __syncthreads();

    // ---- S3: rho (one warp per row, rows strided by 32) ----
    for (int i = wid; i < T; i += 32) {
        const uint4* r16 = (const uint4*)(g_simb + ((size_t)b * T + i) * T);
        float a[11];
#pragma unroll
        for (int k = 0; k < 11; k++) a[k] = -1e30f;
#pragma unroll
        for (int jt = 0; jt < 8; jt++) {
            uint4 v0 = r16[lane + jt * 32];
            __nv_bfloat162 p[4];
            p[0] = *(__nv_bfloat162*)&v0.x; p[1] = *(__nv_bfloat162*)&v0.y;
            p[2] = *(__nv_bfloat162*)&v0.z; p[3] = *(__nv_bfloat162*)&v0.w;
            __nv_bfloat162 m = __hmax2(__hmax2(p[0], p[1]), __hmax2(p[2], p[3]));
            float fm = fmaxf(__low2float(m), __high2float(m));
            if (fm > a[10]) {
#pragma unroll
                for (int q = 0; q < 4; q++) {
                    float lo = __low2float(p[q]), hi = __high2float(p[q]);
                    if (lo > a[10]) ins11(lo, a);
                    if (hi > a[10]) ins11(hi, a);
                }
            }
        }
        float sum = 0.f;
#pragma unroll
        for (int r = 0; r < 11; r++) {
            float h = a[0], m = h;
#pragma unroll
            for (int o = 16; o > 0; o >>= 1)
                m = fmaxf(m, __shfl_xor_sync(full, m, o));
            unsigned msk = __ballot_sync(full, h == m);
            int winner = __ffs(msk) - 1;
            if (lane == winner) {
#pragma unroll
                for (int k = 0; k < 10; k++) a[k] = a[k + 1];
                a[10] = -1e30f;
            }
            if (r > 0) sum += m;            // ranks 1..10 (rank 0 = self)
        }
        if (lane == 0) g_rho[b * T + i] = expf(-sum * (1.0f / KNN));
    }
    __syncthreads();

    // ---- S4: sort rows by rho desc ----
    {
        float* key = (float*)smem;
        int* ord = (int*)(key + T);
        for (int t = tid; t < T; t += 1024) { key[t] = -g_rho[b * T + t]; ord[t] = t; }
        __syncthreads();
        bitonic_sort_shared(key, ord);
        for (int k = tid; k < T; k += 1024) {
            int t = ord[k];
            g_ord[b * T + k] = t;
            g_rank[b * T + t] = k;
        }
    }
    __syncthreads();

    // ---- S5: segment mins over rho-ordered rows ----
    {
        const __nv_bfloat16* S = g_simb + (size_t)b * T * T;
        for (int item = tid; item < 32 * (T / 2); item += 1024) {
            int seg = item >> 10, cp = item & (T / 2 - 1);
            const int* ordp = g_ord + b * T + seg * 64;
            __nv_bfloat162 run = __floats2bfloat162_rn(1e30f, 1e30f);
            for (int k = 0; k < 64; k++) {
                unsigned u = *(const unsigned*)(S + (size_t)ordp[k] * T + cp * 2);
                run = __hmin2(run, *(__nv_bfloat162*)&u);
            }
            g_segmin[((size_t)b * 32 + seg) * (T / 2) + cp] = *(unsigned*)&run;
        }
    }
    __syncthreads();

    // ---- S6: delta fix-up + s = rho*delta ----
    {
        const __nv_bfloat16* S = g_simb + (size_t)b * T * T;
        for (int i = tid; i < T; i += 1024) {
            float rho_i = g_rho[b * T + i];
            int r = g_rank[b * T + i];
            int seg_i = r >> 6;
            float mn = 1e30f;
            const unsigned* segm = g_segmin + (size_t)b * 32 * (T / 2) + (i >> 1);
            for (int s = 0; s < seg_i; s++) {
                unsigned u = segm[(size_t)s * (T / 2)];
                __nv_bfloat162 p = *(__nv_bfloat162*)&u;
                float v = (i & 1) ? __high2float(p) : __low2float(p);
                mn = fminf(mn, v);
            }
            const int* ordp = g_ord + b * T + (seg_i << 6);
            int nown = r - (seg_i << 6);
            for (int k = 0; k < nown; k++) {
                int row = ordp[k];
                if (g_rho[b * T + row] > rho_i)    // strict (matches reference)
                    mn = fminf(mn, __bfloat162float(S[(size_t)row * T + i]));
            }
            float delta = (mn < 1e29f) ? mn
                                       : __bfloat162float(S[(size_t)i * T + i]);
            g_s[b * T + i] = rho_i * delta;
        }
    }
    __syncthreads();

    // ---- S7: clustering (chunked greedy, warp 0 serial core) ----
    {
        float* s_sh = (float*)smem;
        float* key  = s_sh + T;
        int* ordA = (int*)(key + T);
        int* lenA = ordA + T;
        int* staA = lenA + T;
        unsigned* thr_sh = (unsigned*)(staA + T);
        unsigned* asgw = thr_sh + T;
        int* sh_ncl = (int*)(asgw + 66);

        for (int t = tid; t < T; t += 1024) s_sh[t] = g_s[b * T + t];
        for (int t = tid; t < 66; t += 1024) asgw[t] = 0u;
        __syncthreads();

        for (int t = tid; t < T; t += 1024) {
            unsigned m = 0;
            const __nv_bfloat16* row = g_simb + ((size_t)b * T + t) * T;
#pragma unroll
            for (int k = 0; k < 9; k++) {
                if (k == 4) continue;
                int j = t - 4 + k;
                if (j >= 0 && j < T &&
                    (__bfloat162float(row[j]) - BETA * s_sh[j] > THR)) m |= 1u << k;
            }
            thr_sh[t] = m;
        }

        for (int t = tid; t < T; t += 1024) { key[t] = -s_sh[t]; ordA[t] = t; }
        __syncthreads();
        bitonic_sort_shared(key, ordA);

        if (tid < 32) {
            int cid_base = 0;
            for (int p = 0; p < T; p += 32) {
                int seed = ordA[p + lane];
                unsigned thrm = thr_sh[seed];
                int bitpos = seed + 28;
                unsigned w0 = asgw[bitpos >> 5];
                unsigned w1 = asgw[(bitpos >> 5) + 1];
                unsigned A = (unsigned)(((((unsigned long long)w1 << 32) | w0)
                                         >> (bitpos & 31))) & 0x1FFu;
                bool pre = (A >> 4) & 1u;
                bool isfast = !pre && (thrm == 0u);
                bool isslow = !pre && (thrm != 0u);
                unsigned slowm = __ballot_sync(full, isslow);
                bool committed = false;
                int st = seed, sz = 1;

                if (slowm == 0u) {
                    committed = isfast;
                } else {
                    unsigned rem = slowm;
                    while (rem) {
                        int i = __ffs(rem) - 1; rem &= rem - 1;
                        int wb_i = __shfl_sync(full, seed, i) - 4;
                        unsigned contrib = 0u;
                        int lo = -1, hi = -2;
                        if (committed) {
                            lo = max(st, wb_i); hi = min(st + sz - 1, wb_i + 8);
                        } else if (isfast && lane < i) {
                            lo = max(seed, wb_i); hi = min(seed, wb_i + 8);
                        }
                        if (lo <= hi) contrib = ((1u << (hi - lo + 1)) - 1u) << (lo - wb_i);
                        unsigned add = __reduce_or_sync(full, contrib);
                        if (lane == i) {
                            A |= add;
                            if (!((A >> 4) & 1u)) {
                                unsigned avail = thrm & ~A;
                                unsigned f4 = (avail >> 5) & 0xFu;
                                int f = min(__ffs(~f4) - 1, 3);
                                int size = 1 + f;
                                unsigned b4 = __brev(avail & 0xFu) >> 28;
                                int bb = min(__ffs(~b4) - 1, 4 - size);
                                st = seed - bb;
                                sz = size + bb;
                                committed = true;
                            }
                        }
                    }
                    unsigned cm = slowm;
                    bool covered = false;
                    while (cm) {
                        int j = __ffs(cm) - 1; cm &= cm - 1;
                        int stj = __shfl_sync(full, st, j);
                        int szj = __shfl_sync(full, sz, j);
                        int cmj = __shfl_sync(full, (int)committed, j);
                        if (isfast && j < lane && cmj && seed >= stj && seed < stj + szj)
                            covered = true;
                    }
                    if (isfast && !covered) committed = true;
                }

                unsigned cmask = __ballot_sync(full, committed);
                if (committed) {
                    int cid = cid_base + __popc(cmask & ((1u << lane) - 1u));
                    lenA[cid] = sz;
                    staA[cid] = st;
                    int bp = st + 32;
                    unsigned long long m64 = ((1ull << sz) - 1ull) << (bp & 31);
                    atomicOr(&asgw[bp >> 5], (unsigned)m64);
                    unsigned hiw = (unsigned)(m64 >> 32);
                    if (hiw) atomicOr(&asgw[(bp >> 5) + 1], hiw);
                }
                cid_base += __popc(cmask);
                __syncwarp(full);
            }
            if (lane == 0) *sh_ncl = cid_base;
        }
        __syncthreads();

        int ncl = *sh_ncl;
        for (int c = tid; c < T; c += 1024) {
            if (c >= ncl) { lenA[c] = 0; staA[c] = T; }
            key[c] = (float)(staA[c] * 4096 + c);   // stable by start (< 2^24)
            ordA[c] = c;
        }
        __syncthreads();
        bitonic_sort_shared(key, ordA);

        for (int r = tid; r < T; r += 1024) {
            int c = ordA[r];
            g_clen[b * T + r] = lenA[c];
            g_cstart[b * T + r] = staA[c];
        }
    }
    __syncthreads();

    // ---- S8: mean-pool (overwrites the gate's fast-path copy) ----
    for (int idx = tid; idx < D * T; idx += 1024) {
        int d = idx >> 11, r = idx & (T - 1);
        int len = g_clen[b * T + r];
        int st = g_cstart[b * T + r];
        float acc = 0.f;
        for (int k = 0; k < len; k++) acc += x[((size_t)b * D + d) * T + st + k];
        out[(size_t)b * D * T + (size_t)d * T + r] = len ? acc / (float)len : 0.f;
        if (lens_out && d == 0) lens_out[b * T + r] = (float)len;
    }
}

// ---------------- launch ------------------------------------------------------
extern "C" void kernel_launch(void* const* d_in, const int* in_sizes, int n_in,
                              void* d_out, int out_size) {
    const float* x = (const float*)d_in[0];
    float* out = (float*)d_out;
    float* lens_out = (out_size >= (int)(B * D * T + B * T)) ? out + (size_t)B * D * T
                                                             : nullptr;

    const int FB_SMEM = (6 * T + 67) * 4;   // 49420 B arena (max over stages)
    cudaFuncSetAttribute(fallback_kernel,
                         cudaFuncAttributeMaxDynamicSharedMemorySize, FB_SMEM);

    gate_kernel<<<dim3(T / 32, B), 256>>>(x, out, lens_out);
    fallback_kernel<<<B, 1024, FB_SMEM>>>(x, out, lens_out);
}

// round 16
// speedup vs baseline: 21.4963x; 1.1111x over previous
#include <cuda_runtime.h>
#include <cuda_bf16.h>
#include <math.h>

#define B 8
#define D 256
#define T 2048
#define KNN 10
#define BETA 0.2f
#define THR 0.7f

// ---------------- scratch (device globals; no allocations allowed) ----------
__device__ float g_invn[B * T];
__device__ __nv_bfloat16 g_xnb[B * T * D];     // fallback only
__device__ __nv_bfloat16 g_simb[B * T * T];    // fallback only
__device__ float g_rho[B * T];
__device__ float g_s[B * T];
__device__ int   g_ord[B * T];
__device__ int   g_rank[B * T];
__device__ unsigned g_segmin[B * 32 * (T / 2)];
__device__ int   g_cstart[B * T];
__device__ int   g_clen[B * T];
// 0 = all-singleton fast path. Statically zero; monotonic: set only when the
// gate trips, and for such an input it trips identically on every replay.
__device__ int   g_flag;

// ---------------- 1) gate + norms + fast-path copy ---------------------------
// Growth needs sim - BETA*s > THR with s >= 0 (rho>0, delta in [0,1]), hence
// sim > THR on the +/-4 band. Gate conservatively at sim > 0.68 (dot > 0.36).
// Writes out = x and lens = 1 unconditionally (exact on the fast path); the
// guarded fallback overwrites both when the gate trips.
// Layout: block = 512 thr (16 warps), covers a 128-t span x all 256 d.
// Lane owns 4 consecutive t (float4); neighbor window via 4 shfl + lane-31 halo.
__global__ void __launch_bounds__(512) gate_kernel(const float* __restrict__ x,
                                                   float* __restrict__ out,
                                                   float* lens_out) {
    const unsigned full = 0xffffffffu;
    int b = blockIdx.y, t0 = blockIdx.x * 128;
    int tid = threadIdx.x;
    int w = tid >> 5, lane = tid & 31;
    const float* xb = x + (size_t)b * D * T;
    float* ob = out + (size_t)b * D * T;

    float dot[4][4];                 // [i][off-1], i = t position within float4
    float nrm[4] = {0.f, 0.f, 0.f, 0.f};
    float hnrm[4] = {0.f, 0.f, 0.f, 0.f};   // lane 31 only: halo norms
#pragma unroll
    for (int i = 0; i < 4; i++)
#pragma unroll
        for (int o = 0; o < 4; o++) dot[i][o] = 0.f;

    bool has_halo = (t0 + 128 < T);
    for (int d = w; d < D; d += 16) {
        const float* rowp = xb + (size_t)d * T + t0;
        float4 v = *(const float4*)(rowp + 4 * lane);
        *(float4*)(ob + (size_t)d * T + t0 + 4 * lane) = v;   // out = x copy
        float4 h = make_float4(0.f, 0.f, 0.f, 0.f);
        if (lane == 31 && has_halo) h = *(const float4*)(rowp + 128);
        float4 n;
        n.x = __shfl_down_sync(full, v.x, 1);
        n.y = __shfl_down_sync(full, v.y, 1);
        n.z = __shfl_down_sync(full, v.z, 1);
        n.w = __shfl_down_sync(full, v.w, 1);
        if (lane == 31) n = h;
        float s[8] = {v.x, v.y, v.z, v.w, n.x, n.y, n.z, n.w};
#pragma unroll
        for (int i = 0; i < 4; i++) {
            nrm[i] += s[i] * s[i];
#pragma unroll
            for (int off = 1; off <= 4; off++)
                dot[i][off - 1] += s[i] * s[i + off];
        }
        if (lane == 31) {
            hnrm[0] += n.x * n.x; hnrm[1] += n.y * n.y;
            hnrm[2] += n.z * n.z; hnrm[3] += n.w * n.w;
        }
    }

    // cross-warp (d-split) reduction
    __shared__ float red[16][5][128];    // [warp][{norm,dot1..4}][t_local]
    __shared__ float redh[16][4];
    __shared__ float inv_sh[128];
    __shared__ float invh_sh[4];
#pragma unroll
    for (int i = 0; i < 4; i++) {
        red[w][0][4 * lane + i] = nrm[i];
#pragma unroll
        for (int o = 0; o < 4; o++) red[w][1 + o][4 * lane + i] = dot[i][o];
    }
    if (lane == 31) {
#pragma unroll
        for (int j = 0; j < 4; j++) redh[w][j] = hnrm[j];
    }
    __syncthreads();

    for (int e = tid; e < 640; e += 512) {
        int c = e >> 7, t = e & 127;
        float s = 0.f;
#pragma unroll
        for (int ww = 0; ww < 16; ww++) s += red[ww][c][t];
        red[0][c][t] = s;        // each (c,t) touched by exactly one thread
    }
    if (tid < 4) {
        float s = 0.f;
#pragma unroll
        for (int ww = 0; ww < 16; ww++) s += redh[ww][tid];
        invh_sh[tid] = 1.f / fmaxf(sqrtf(s), 1e-12f);
    }
    __syncthreads();

    if (tid < 128) {
        int t = t0 + tid;
        float invn = 1.f / fmaxf(sqrtf(red[0][0][tid]), 1e-12f);
        g_invn[b * T + t] = invn;              // fallback needs this
        if (lens_out) lens_out[b * T + t] = 1.0f;   // fast-path lens
        inv_sh[tid] = invn;
    }
    __syncthreads();

    if (tid < 128) {
        int t = t0 + tid;
        float invn = inv_sh[tid];
        float mx = -1.f;
#pragma unroll
        for (int off = 1; off <= 4; off++) {
            if (t + off < T) {
                float invo = (tid + off < 128) ? inv_sh[tid + off]
                                               : invh_sh[tid + off - 128];
                mx = fmaxf(mx, red[0][off][tid] * invn * invo);
            }
        }
        if (mx > 0.36f) atomicOr(&g_flag, 1);   // sim=(dot+1)/2 > 0.68
    }
}

// ---------------- helpers (fallback) -----------------------------------------
__device__ __forceinline__ void bitonic_sort_shared(float* key, int* ord) {
    for (int k = 2; k <= T; k <<= 1) {
        for (int j = k >> 1; j > 0; j >>= 1) {
            for (int i = threadIdx.x; i < T; i += 1024) {
                int l = i ^ j;
                if (l > i) {
                    bool up = ((i & k) == 0);
                    float ki = key[i], kl = key[l];
                    int oi = ord[i], ol = ord[l];
                    bool iAfter = (ki > kl) || (ki == kl && oi > ol);
                    if (iAfter == up) {
                        key[i] = kl; key[l] = ki;
                        ord[i] = ol; ord[l] = oi;
                    }
                }
            }
            __syncthreads();
        }
    }
}

__device__ __forceinline__ void ins11(float v, float* a) {
#pragma unroll
    for (int k = 0; k < 11; k++) {
        if (v > a[k]) { float tmp = a[k]; a[k] = v; v = tmp; }
    }
}

// ---------------- 2) fallback mega-kernel (one block per batch) --------------
// Every stage of the reference pipeline is batch-local, so one 1024-thread
// block per batch runs the whole fallback with __syncthreads() between stages.
// Never executes for gate-clean inputs; correctness (not speed) is its job.
__global__ void __launch_bounds__(1024) fallback_kernel(const float* __restrict__ x,
                                                        float* __restrict__ out,
                                                        float* lens_out) {
    if (g_flag == 0) return;
    extern __shared__ char smem[];
    int b = blockIdx.x;
    int tid = threadIdx.x;
    int wid = tid >> 5, lane = tid & 31;
    const unsigned full = 0xffffffffu;

    // ---- S1: transpose + normalize -> xnb[b] ----
    for (int idx = tid; idx < T * D; idx += 1024) {
        int t = idx >> 8, d = idx & 255;               // D = 256
        g_xnb[((size_t)b * T + t) * D + d] =
            __float2bfloat16(x[(size_t)b * D * T + (size_t)d * T + t] * g_invn[b * T + t]);
    }
    __syncthreads();

    // ---- S2: sim = (xn @ xn^T + 1)/2, bf16 store (SIMT; fallback-speed) ----
    {
        const __nv_bfloat16* Ab = g_xnb + (size_t)b * T * D;
        __nv_bfloat16* C = g_simb + (size_t)b * T * T;
        for (int ij = tid; ij < T * T; ij += 1024) {
            int i = ij >> 11, j = ij & (T - 1);
            const __nv_bfloat162* ar = (const __nv_bfloat162*)(Ab + (size_t)i * D);
            const __nv_bfloat162* br = (const __nv_bfloat162*)(Ab + (size_t)j * D);
            float acc = 0.f;
#pragma unroll 8
            for (int k = 0; k < D / 2; k++) {
                float2 fa = __bfloat1622float2(ar[k]);
                float2 fb = __bfloat1622float2(br[k]);
                acc += fa.x * fb.x + fa.y * fb.y;
            }
            C[(size_t)i * T + j] = __float2bfloat16((acc + 1.f) * 0.5f);
        }
    }
    __syncthreads();

    // ---- S3: rho (one warp per row, rows strided by 32) ----
    for (int i = wid; i < T; i += 32) {
        const uint4* r16 = (const uint4*)(g_simb + ((size_t)b * T + i) * T);
        float a[11];
#pragma unroll
        for (int k = 0; k < 11; k++) a[k] = -1e30f;
#pragma unroll
        for (int jt = 0; jt < 8; jt++) {
            uint4 v0 = r16[lane + jt * 32];
            __nv_bfloat162 p[4];
            p[0] = *(__nv_bfloat162*)&v0.x; p[1] = *(__nv_bfloat162*)&v0.y;
            p[2] = *(__nv_bfloat162*)&v0.z; p[3] = *(__nv_bfloat162*)&v0.w;
            __nv_bfloat162 m = __hmax2(__hmax2(p[0], p[1]), __hmax2(p[2], p[3]));
            float fm = fmaxf(__low2float(m), __high2float(m));
            if (fm > a[10]) {
#pragma unroll
                for (int q = 0; q < 4; q++) {
                    float lo = __low2float(p[q]), hi = __high2float(p[q]);
                    if (lo > a[10]) ins11(lo, a);
                    if (hi > a[10]) ins11(hi, a);
                }
            }
        }
        float sum = 0.f;
#pragma unroll
        for (int r = 0; r < 11; r++) {
            float h = a[0], m = h;
#pragma unroll
            for (int o = 16; o > 0; o >>= 1)
                m = fmaxf(m, __shfl_xor_sync(full, m, o));
            unsigned msk = __ballot_sync(full, h == m);
            int winner = __ffs(msk) - 1;
            if (lane == winner) {
#pragma unroll
                for (int k = 0; k < 10; k++) a[k] = a[k + 1];
                a[10] = -1e30f;
            }
            if (r > 0) sum += m;            // ranks 1..10 (rank 0 = self)
        }
        if (lane == 0) g_rho[b * T + i] = expf(-sum * (1.0f / KNN));
    }
    __syncthreads();

    // ---- S4: sort rows by rho desc ----
    {
        float* key = (float*)smem;
        int* ord = (int*)(key + T);
        for (int t = tid; t < T; t += 1024) { key[t] = -g_rho[b * T + t]; ord[t] = t; }
        __syncthreads();
        bitonic_sort_shared(key, ord);
        for (int k = tid; k < T; k += 1024) {
            int t = ord[k];
            g_ord[b * T + k] = t;
            g_rank[b * T + t] = k;
        }
    }
    __syncthreads();

    // ---- S5: segment mins over rho-ordered rows ----
    {
        const __nv_bfloat16* S = g_simb + (size_t)b * T * T;
        for (int item = tid; item < 32 * (T / 2); item += 1024) {
            int seg = item >> 10, cp = item & (T / 2 - 1);
            const int* ordp = g_ord + b * T + seg * 64;
            __nv_bfloat162 run = __floats2bfloat162_rn(1e30f, 1e30f);
            for (int k = 0; k < 64; k++) {
                unsigned u = *(const unsigned*)(S + (size_t)ordp[k] * T + cp * 2);
                run = __hmin2(run, *(__nv_bfloat162*)&u);
            }
            g_segmin[((size_t)b * 32 + seg) * (T / 2) + cp] = *(unsigned*)&run;
        }
    }
    __syncthreads();

    // ---- S6: delta fix-up + s = rho*delta ----
    {
        const __nv_bfloat16* S = g_simb + (size_t)b * T * T;
        for (int i = tid; i < T; i += 1024) {
            float rho_i = g_rho[b * T + i];
            int r = g_rank[b * T + i];
            int seg_i = r >> 6;
            float mn = 1e30f;
            const unsigned* segm = g_segmin + (size_t)b * 32 * (T / 2) + (i >> 1);
            for (int s = 0; s < seg_i; s++) {
                unsigned u = segm[(size_t)s * (T / 2)];
                __nv_bfloat162 p = *(__nv_bfloat162*)&u;
                float v = (i & 1) ? __high2float(p) : __low2float(p);
                mn = fminf(mn, v);
            }
            const int* ordp = g_ord + b * T + (seg_i << 6);
            int nown = r - (seg_i << 6);
            for (int k = 0; k < nown; k++) {
                int row = ordp[k];
                if (g_rho[b * T + row] > rho_i)    // strict (matches reference)
                    mn = fminf(mn, __bfloat162float(S[(size_t)row * T + i]));
            }
            float delta = (mn < 1e29f) ? mn
                                       : __bfloat162float(S[(size_t)i * T + i]);
            g_s[b * T + i] = rho_i * delta;
        }
    }
    __syncthreads();

    // ---- S7: clustering (chunked greedy, warp 0 serial core) ----
    {
        float* s_sh = (float*)smem;
        float* key  = s_sh + T;
        int* ordA = (int*)(key + T);
        int* lenA = ordA + T;
        int* staA = lenA + T;
        unsigned* thr_sh = (unsigned*)(staA + T);
        unsigned* asgw = thr_sh + T;
        int* sh_ncl = (int*)(asgw + 66);

        for (int t = tid; t < T; t += 1024) s_sh[t] = g_s[b * T + t];
        for (int t = tid; t < 66; t += 1024) asgw[t] = 0u;
        __syncthreads();

        for (int t = tid; t < T; t += 1024) {
            unsigned m = 0;
            const __nv_bfloat16* row = g_simb + ((size_t)b * T + t) * T;
#pragma unroll
            for (int k = 0; k < 9; k++) {
                if (k == 4) continue;
                int j = t - 4 + k;
                if (j >= 0 && j < T &&
                    (__bfloat162float(row[j]) - BETA * s_sh[j] > THR)) m |= 1u << k;
            }
            thr_sh[t] = m;
        }

        for (int t = tid; t < T; t += 1024) { key[t] = -s_sh[t]; ordA[t] = t; }
        __syncthreads();
        bitonic_sort_shared(key, ordA);

        if (tid < 32) {
            int cid_base = 0;
            for (int p = 0; p < T; p += 32) {
                int seed = ordA[p + lane];
                unsigned thrm = thr_sh[seed];
                int bitpos = seed + 28;
                unsigned w0 = asgw[bitpos >> 5];
                unsigned w1 = asgw[(bitpos >> 5) + 1];
                unsigned A = (unsigned)(((((unsigned long long)w1 << 32) | w0)
                                         >> (bitpos & 31))) & 0x1FFu;
                bool pre = (A >> 4) & 1u;
                bool isfast = !pre && (thrm == 0u);
                bool isslow = !pre && (thrm != 0u);
                unsigned slowm = __ballot_sync(full, isslow);
                bool committed = false;
                int st = seed, sz = 1;

                if (slowm == 0u) {
                    committed = isfast;
                } else {
                    unsigned rem = slowm;
                    while (rem) {
                        int i = __ffs(rem) - 1; rem &= rem - 1;
                        int wb_i = __shfl_sync(full, seed, i) - 4;
                        unsigned contrib = 0u;
                        int lo = -1, hi = -2;
                        if (committed) {
                            lo = max(st, wb_i); hi = min(st + sz - 1, wb_i + 8);
                        } else if (isfast && lane < i) {
                            lo = max(seed, wb_i); hi = min(seed, wb_i + 8);
                        }
                        if (lo <= hi) contrib = ((1u << (hi - lo + 1)) - 1u) << (lo - wb_i);
                        unsigned add = __reduce_or_sync(full, contrib);
                        if (lane == i) {
                            A |= add;
                            if (!((A >> 4) & 1u)) {
                                unsigned avail = thrm & ~A;
                                unsigned f4 = (avail >> 5) & 0xFu;
                                int f = min(__ffs(~f4) - 1, 3);
                                int size = 1 + f;
                                unsigned b4 = __brev(avail & 0xFu) >> 28;
                                int bb = min(__ffs(~b4) - 1, 4 - size);
                                st = seed - bb;
                                sz = size + bb;
                                committed = true;
                            }
                        }
                    }
                    unsigned cm = slowm;
                    bool covered = false;
                    while (cm) {
                        int j = __ffs(cm) - 1; cm &= cm - 1;
                        int stj = __shfl_sync(full, st, j);
                        int szj = __shfl_sync(full, sz, j);
                        int cmj = __shfl_sync(full, (int)committed, j);
                        if (isfast && j < lane && cmj && seed >= stj && seed < stj + szj)
                            covered = true;
                    }
                    if (isfast && !covered) committed = true;
                }

                unsigned cmask = __ballot_sync(full, committed);
                if (committed) {
                    int cid = cid_base + __popc(cmask & ((1u << lane) - 1u));
                    lenA[cid] = sz;
                    staA[cid] = st;
                    int bp = st + 32;
                    unsigned long long m64 = ((1ull << sz) - 1ull) << (bp & 31);
                    atomicOr(&asgw[bp >> 5], (unsigned)m64);
                    unsigned hiw = (unsigned)(m64 >> 32);
                    if (hiw) atomicOr(&asgw[(bp >> 5) + 1], hiw);
                }
                cid_base += __popc(cmask);
                __syncwarp(full);
            }
            if (lane == 0) *sh_ncl = cid_base;
        }
        __syncthreads();

        int ncl = *sh_ncl;
        for (int c = tid; c < T; c += 1024) {
            if (c >= ncl) { lenA[c] = 0; staA[c] = T; }
            key[c] = (float)(staA[c] * 4096 + c);   // stable by start (< 2^24)
            ordA[c] = c;
        }
        __syncthreads();
        bitonic_sort_shared(key, ordA);

        for (int r = tid; r < T; r += 1024) {
            int c = ordA[r];
            g_clen[b * T + r] = lenA[c];
            g_cstart[b * T + r] = staA[c];
        }
    }
    __syncthreads();

    // ---- S8: mean-pool (overwrites the gate's fast-path copy) ----
    for (int idx = tid; idx < D * T; idx += 1024) {
        int d = idx >> 11, r = idx & (T - 1);
        int len = g_clen[b * T + r];
        int st = g_cstart[b * T + r];
        float acc = 0.f;
        for (int k = 0; k < len; k++) acc += x[((size_t)b * D + d) * T + st + k];
        out[(size_t)b * D * T + (size_t)d * T + r] = len ? acc / (float)len : 0.f;
        if (lens_out && d == 0) lens_out[b * T + r] = (float)len;
    }
}

// ---------------- launch ------------------------------------------------------
extern "C" void kernel_launch(void* const* d_in, const int* in_sizes, int n_in,
                              void* d_out, int out_size) {
    const float* x = (const float*)d_in[0];
    float* out = (float*)d_out;
    float* lens_out = (out_size >= (int)(B * D * T + B * T)) ? out + (size_t)B * D * T
                                                             : nullptr;

    const int FB_SMEM = (6 * T + 67) * 4;   // 49420 B arena (max over stages)
    cudaFuncSetAttribute(fallback_kernel,
                         cudaFuncAttributeMaxDynamicSharedMemorySize, FB_SMEM);

    gate_kernel<<<dim3(T / 128, B), 512>>>(x, out, lens_out);
    fallback_kernel<<<B, 1024, FB_SMEM>>>(x, out, lens_out);
}